// round 14
// baseline (speedup 1.0000x reference)
#include <cuda_runtime.h>
#include <cuda_fp16.h>
#include <cstdint>
#include <math.h>

// ---------------- problem constants ----------------
#define BATCH 4
#define NPTS  4096
#define BN    (BATCH*NPTS)          // 16384
#define DP    128
#define DM    256
#define KNN_K 16
#define BNK   (BN*KNN_K)            // 262144
#define INV_SCALE 0.0625f           // 1/sqrt(256)
#define KVS   512                   // row stride of merged kg|vf buffer

// ---------------- device scratch ----------------
__device__ int    g_knn[BNK];                // GLOBAL point index
__device__ float4 g_sp4[BN];                 // xyz2 + norm
__device__ __half g_f1h[BN * DP];
__device__ __half g_f2h[BN * DP];
__device__ __half g_x1h[BN * DM];
__device__ __half g_x2h[BN * DM];
__device__ float  g_qg [BN * DM];
__device__ float  g_kgvf[BN * KVS];          // cols 0-255: x2@(Wk Wg1); 256-511: x2@Wv
__device__ __half g_resh[BN * DM];
__device__ __half g_t2h[(size_t)BNK * DM];
__device__ __half g_peh[(size_t)BNK * DM];   // pos_enc in fp16 (epilogue-consumed)
// fp16 weights, [N rows][K cols] K-major
__device__ __half g_wfc1h[DM * DP];
__device__ __half g_wfc2h[DP * DM];
__device__ __half g_wdualh[2 * DM * DM];
__device__ __half g_wg2h [DM * DM];
__device__ __half g_wqgh [DM * DM];
__device__ __half g_wkvh [2 * DM * DM];
__device__ float  g_cc [DM];

// ---------------- PTX helpers ----------------
__device__ __forceinline__ uint32_t smem_u32(const void* p) {
    uint32_t a;
    asm("{ .reg .u64 t; cvta.to.shared.u64 t, %1; cvt.u32.u64 %0, t; }" : "=r"(a) : "l"(p));
    return a;
}
#define CP16(dst, src) \
    asm volatile("cp.async.cg.shared.global [%0], [%1], 16;" :: "r"(dst), "l"(src))
#define CP_COMMIT() asm volatile("cp.async.commit_group;" ::: "memory")
template <int N> __device__ __forceinline__ void cp_wait() {
    asm volatile("cp.async.wait_group %0;" :: "n"(N) : "memory");
}
#define LDSM_X4(r0, r1, r2, r3, addr) \
    asm volatile("ldmatrix.sync.aligned.m8n8.x4.shared.b16 {%0,%1,%2,%3}, [%4];" \
        : "=r"(r0), "=r"(r1), "=r"(r2), "=r"(r3) : "r"(addr))

__device__ __forceinline__ void mma_f16(float* d, const uint32_t* a, const uint32_t* b) {
    asm volatile(
        "mma.sync.aligned.m16n8k16.row.col.f32.f16.f16.f32 "
        "{%0,%1,%2,%3},{%4,%5,%6,%7},{%8,%9},{%0,%1,%2,%3};"
        : "+f"(d[0]), "+f"(d[1]), "+f"(d[2]), "+f"(d[3])
        : "r"(a[0]), "r"(a[1]), "r"(a[2]), "r"(a[3]), "r"(b[0]), "r"(b[1]));
}

__device__ __forceinline__ float rmax8(float v) {
    v = fmaxf(v, __shfl_xor_sync(0xffffffffu, v, 4));
    v = fmaxf(v, __shfl_xor_sync(0xffffffffu, v, 8));
    v = fmaxf(v, __shfl_xor_sync(0xffffffffu, v, 16));
    return v;
}
__device__ __forceinline__ float rsum8(float v) {
    v += __shfl_xor_sync(0xffffffffu, v, 4);
    v += __shfl_xor_sync(0xffffffffu, v, 8);
    v += __shfl_xor_sync(0xffffffffu, v, 16);
    return v;
}

// ---------------- prep kernels ----------------
__global__ void prep_pts(const float* __restrict__ xyz2, float4* __restrict__ sp4)
{
    int i = blockIdx.x * 256 + threadIdx.x;
    float x = xyz2[3*i], y = xyz2[3*i+1], z = xyz2[3*i+2];
    sp4[i] = make_float4(x, y, z, x*x + y*y + z*z);
}

__global__ void f2h_kernel(const float* __restrict__ in, __half* __restrict__ out)
{
    int i = (blockIdx.x * 256 + threadIdx.x) * 4;
    float4 v = *reinterpret_cast<const float4*>(in + i);
    __half2* o = reinterpret_cast<__half2*>(out + i);
    o[0] = __floats2half2_rn(v.x, v.y);
    o[1] = __floats2half2_rn(v.z, v.w);
}

__global__ void transpose_kernel(const float* __restrict__ W, __half* __restrict__ WT,
                                 int K, int N)
{
    __shared__ float t[32][33];
    int bx = blockIdx.x * 32, by = blockIdx.y * 32;
    int tx = threadIdx.x, ty = threadIdx.y;
#pragma unroll
    for (int i = 0; i < 32; i += 8)
        t[ty + i][tx] = W[(size_t)(by + ty + i) * N + bx + tx];
    __syncthreads();
#pragma unroll
    for (int i = 0; i < 32; i += 8)
        WT[(size_t)(bx + ty + i) * K + by + tx] = __float2half(t[tx][ty + i]);
}

__global__ void combine_kernel(const float* __restrict__ W1, const float* __restrict__ W2,
                               __half* __restrict__ outT)
{
    __shared__ float colv[DM];
    int n = blockIdx.x, k = threadIdx.x;
    colv[k] = W2[k * DM + n];
    __syncthreads();
    const float* w = W1 + k * DM;
    float s = 0.0f;
#pragma unroll 8
    for (int m = 0; m < DM; m++) s = fmaf(w[m], colv[m], s);
    outT[n * DM + k] = __float2half(s);
}

__global__ void cc_kernel(const float* __restrict__ bd2, const float* __restrict__ Wg1,
                          const float* __restrict__ bg1, float* __restrict__ cc)
{
    int n = threadIdx.x;
    float s = bg1[n];
#pragma unroll 8
    for (int m = 0; m < DM; m++) s = fmaf(bd2[m], Wg1[m * DM + n], s);
    cc[n] = s;
}

// ---------------- KNN: register ladder, 8 threads/query, 8-way smem merge ----------------
// smem: sd[8][33][32] floats + si same = 67584 B
#define KNN_SMEM (2 * 8 * 33 * 32 * 4)

__global__ __launch_bounds__(256) void knn_kernel(
    const float* __restrict__ xyz1, const float4* __restrict__ sp4g,
    int* __restrict__ knn)
{
    extern __shared__ __align__(16) float ks[];
    float* sd = ks;                       // [sub][k][q]
    int*   si = (int*)(ks + 8 * 33 * 32);

    const int tid = threadIdx.x;
    const int q   = tid & 31;             // query lane 0..31
    const int sub = tid >> 5;             // candidate sub-range 0..7
    const int qg  = blockIdx.x * 32 + q;  // global query
    const int b   = qg >> 12;

    const float qx = xyz1[3*qg], qy = xyz1[3*qg+1], qz = xyz1[3*qg+2];
    const float qn = qx*qx + qy*qy + qz*qz;

    float bd[32]; int bi[32];
#pragma unroll
    for (int i = 0; i < 32; i++) { bd[i] = 3.4e38f; bi[i] = 0; }

    const float4* sp = sp4g + b * NPTS + sub * 512;
    const int jbase = sub * 512;
    for (int t = 0; t < 512; t++) {
        float4 c = __ldg(sp + t);
        float d = qn + c.w - 2.0f * (qx*c.x + qy*c.y + qz*c.z);
        if (d < bd[31]) {                 // strict < : stable tie order
            int j = jbase + t;
            bool pr = true;
#pragma unroll
            for (int p = 31; p > 0; p--) {
                bool sh = d < bd[p-1];
                float vv = sh ? bd[p-1] : d;
                int   ii = sh ? bi[p-1] : j;
                if (pr) { bd[p] = vv; bi[p] = ii; }
                pr = sh;
            }
            if (pr) { bd[0] = d; bi[0] = j; }
        }
    }

#pragma unroll
    for (int k = 0; k < 32; k++) {
        sd[(sub * 33 + k) * 32 + q] = bd[k];
        si[(sub * 33 + k) * 32 + q] = bi[k];
    }
    sd[(sub * 33 + 32) * 32 + q] = 3.4e38f;       // sentinel
    si[(sub * 33 + 32) * 32 + q] = 0x7fffffff;
    __syncthreads();

    // 8-way lexicographic merge, one thread per query
    if (tid < 32) {
        const int qq = tid;
        const int qgl = blockIdx.x * 32 + qq;
        const int base = (qgl >> 12) * NPTS;
        int c0=0,c1=0,c2=0,c3=0,c4=0,c5=0,c6=0,c7=0;
        float d0=sd[(0*33)*32+qq], d1=sd[(1*33)*32+qq], d2=sd[(2*33)*32+qq], d3=sd[(3*33)*32+qq];
        float d4=sd[(4*33)*32+qq], d5=sd[(5*33)*32+qq], d6=sd[(6*33)*32+qq], d7=sd[(7*33)*32+qq];
        int   i0=si[(0*33)*32+qq], i1=si[(1*33)*32+qq], i2=si[(2*33)*32+qq], i3=si[(3*33)*32+qq];
        int   i4=si[(4*33)*32+qq], i5=si[(5*33)*32+qq], i6=si[(6*33)*32+qq], i7=si[(7*33)*32+qq];
        int* o = knn + (size_t)qgl * KNN_K;
#pragma unroll 1
        for (int r = 0; r < 32; r++) {
            float bdv = d0; int biv = i0; int sel = 0;
            if (d1 < bdv || (d1 == bdv && i1 < biv)) { bdv = d1; biv = i1; sel = 1; }
            if (d2 < bdv || (d2 == bdv && i2 < biv)) { bdv = d2; biv = i2; sel = 2; }
            if (d3 < bdv || (d3 == bdv && i3 < biv)) { bdv = d3; biv = i3; sel = 3; }
            if (d4 < bdv || (d4 == bdv && i4 < biv)) { bdv = d4; biv = i4; sel = 4; }
            if (d5 < bdv || (d5 == bdv && i5 < biv)) { bdv = d5; biv = i5; sel = 5; }
            if (d6 < bdv || (d6 == bdv && i6 < biv)) { bdv = d6; biv = i6; sel = 6; }
            if (d7 < bdv || (d7 == bdv && i7 < biv)) { bdv = d7; biv = i7; sel = 7; }
            if (!(r & 1)) o[r >> 1] = base + biv;   // even ranks only
            if      (sel == 0) { c0++; d0 = sd[(0*33+c0)*32+qq]; i0 = si[(0*33+c0)*32+qq]; }
            else if (sel == 1) { c1++; d1 = sd[(1*33+c1)*32+qq]; i1 = si[(1*33+c1)*32+qq]; }
            else if (sel == 2) { c2++; d2 = sd[(2*33+c2)*32+qq]; i2 = si[(2*33+c2)*32+qq]; }
            else if (sel == 3) { c3++; d3 = sd[(3*33+c3)*32+qq]; i3 = si[(3*33+c3)*32+qq]; }
            else if (sel == 4) { c4++; d4 = sd[(4*33+c4)*32+qq]; i4 = si[(4*33+c4)*32+qq]; }
            else if (sel == 5) { c5++; d5 = sd[(5*33+c5)*32+qq]; i5 = si[(5*33+c5)*32+qq]; }
            else if (sel == 6) { c6++; d6 = sd[(6*33+c6)*32+qq]; i6 = si[(6*33+c6)*32+qq]; }
            else               { c7++; d7 = sd[(7*33+c7)*32+qq]; i7 = si[(7*33+c7)*32+qq]; }
        }
    }
}

// ---------------- fp16 GEMM config ----------------
#define KC 64
#define SH 72
#define STG_B 18432
#define NSTAGE 3
#define GEMM_SMEM (NSTAGE * 2 * STG_B)

template<int MODE, bool OUTH>
__global__ __launch_bounds__(256, 2) void gemm_h(
    int M, int N, int K,
    const __half* __restrict__ A, const __half* __restrict__ WT,
    const float* __restrict__ bias, const float* __restrict__ extra,
    void* __restrict__ Cout,
    const __half* __restrict__ pe, const float* __restrict__ vf,
    __half* __restrict__ resh, const int* __restrict__ knn)
{
    extern __shared__ __align__(16) char smraw[];
    const uint32_t sbase = smem_u32(smraw);

    const int tid = threadIdx.x;
    const int bm = blockIdx.y * 128, bn = blockIdx.x * 128;
    const int lane = tid & 31, gid = lane >> 2, tig = lane & 3;
    const int w = tid >> 5, wm = w & 1, wn = w >> 1;
    const int lg = lane >> 3;

    const uint32_t aoff = ((uint32_t)(wm * 64 + (lg & 1) * 8 + (lane & 7)) * SH
                           + (lg >> 1) * 8) * 2;
    const uint32_t boff = ((uint32_t)(wn * 32 + (lg >> 1) * 8 + (lane & 7)) * SH
                           + (lg & 1) * 8) * 2;

    float acc[4][4][4];
#pragma unroll
    for (int i = 0; i < 4; i++)
#pragma unroll
        for (int j = 0; j < 4; j++)
#pragma unroll
            for (int r = 0; r < 4; r++) acc[i][j][r] = 0.0f;

    const int Cn = K / KC;
    const int cprow = tid >> 1;
    const int cpho  = (tid & 1) * 32;

    auto issue = [&](int c) {
        uint32_t st = sbase + (uint32_t)(c % NSTAGE) * (2 * STG_B);
        uint32_t bs = st + STG_B;
        const __half* Ag = A  + (size_t)(bm + cprow) * K + c * KC + cpho;
        const __half* Bg = WT + (size_t)(bn + cprow) * K + c * KC + cpho;
        uint32_t so = (uint32_t)(cprow * SH + cpho) * 2;
#pragma unroll
        for (int t = 0; t < 4; t++) {
            CP16(st + so + 16 * t, Ag + 8 * t);
            CP16(bs + so + 16 * t, Bg + 8 * t);
        }
        CP_COMMIT();
    };

    issue(0);
    issue(1);
    for (int c = 0; c < Cn; c++) {
        if (c == Cn - 1) cp_wait<0>(); else cp_wait<1>();
        __syncthreads();
        if (c + 2 < Cn) issue(c + 2);

        const uint32_t abase = sbase + (uint32_t)(c % NSTAGE) * (2 * STG_B) + aoff;
        const uint32_t bbase = sbase + (uint32_t)(c % NSTAGE) * (2 * STG_B) + STG_B + boff;

#pragma unroll
        for (int kk = 0; kk < 4; kk++) {
            uint32_t af[4][4], bf[4][2];
#pragma unroll
            for (int i = 0; i < 4; i++)
                LDSM_X4(af[i][0], af[i][1], af[i][2], af[i][3],
                        abase + i * (16 * SH * 2) + kk * 32);
#pragma unroll
            for (int jp = 0; jp < 2; jp++)
                LDSM_X4(bf[2*jp][0], bf[2*jp][1], bf[2*jp+1][0], bf[2*jp+1][1],
                        bbase + jp * (16 * SH * 2) + kk * 32);
#pragma unroll
            for (int i = 0; i < 4; i++)
#pragma unroll
                for (int j = 0; j < 4; j++)
                    mma_f16(acc[i][j], af[i], bf[j]);
        }
    }

    const int rowbase = bm + wm * 64;
    const int colbase = bn + wn * 32 + tig * 2;

    if constexpr (MODE == 0) {
#pragma unroll
        for (int i = 0; i < 4; i++) {
            int r0 = rowbase + i * 16 + gid;
#pragma unroll
            for (int j = 0; j < 4; j++) {
                int col = colbase + j * 8;
                float2 v0 = make_float2(acc[i][j][0], acc[i][j][1]);
                float2 v1 = make_float2(acc[i][j][2], acc[i][j][3]);
                if (bias) {
                    float2 bb = *reinterpret_cast<const float2*>(bias + col);
                    v0.x += bb.x; v0.y += bb.y; v1.x += bb.x; v1.y += bb.y;
                }
                if (extra) {
                    float2 e0 = *reinterpret_cast<const float2*>(extra + (size_t)r0 * N + col);
                    float2 e1 = *reinterpret_cast<const float2*>(extra + (size_t)(r0 + 8) * N + col);
                    v0.x += e0.x; v0.y += e0.y; v1.x += e1.x; v1.y += e1.y;
                }
                if (OUTH) {
                    __half* Ch = (__half*)Cout;
                    *reinterpret_cast<__half2*>(Ch + (size_t)r0 * N + col) = __floats2half2_rn(v0.x, v0.y);
                    *reinterpret_cast<__half2*>(Ch + (size_t)(r0 + 8) * N + col) = __floats2half2_rn(v1.x, v1.y);
                } else {
                    float* Cf = (float*)Cout;
                    *reinterpret_cast<float2*>(Cf + (size_t)r0 * N + col) = v0;
                    *reinterpret_cast<float2*>(Cf + (size_t)(r0 + 8) * N + col) = v1;
                }
            }
        }
    } else {  // MODE 2
        float* Cf = (float*)Cout;
#pragma unroll
        for (int i = 0; i < 4; i++) {
            int r0 = rowbase + i * 16 + gid;
            int r1 = r0 + 8;
            int n = r0 >> 4;
            int j1 = knn[r0], j2 = knn[r1];
#pragma unroll
            for (int j = 0; j < 4; j++) {
                int col = colbase + j * 8;
                float2 bb = *reinterpret_cast<const float2*>(bias + col);
                float a0 = acc[i][j][0] + bb.x;
                float a1 = acc[i][j][1] + bb.y;
                float a2 = acc[i][j][2] + bb.x;
                float a3 = acc[i][j][3] + bb.y;
                float m0 = rmax8(fmaxf(a0, a2));
                float m1 = rmax8(fmaxf(a1, a3));
                float e0 = __expf((a0 - m0) * INV_SCALE);
                float e1 = __expf((a1 - m1) * INV_SCALE);
                float e2 = __expf((a2 - m0) * INV_SCALE);
                float e3 = __expf((a3 - m1) * INV_SCALE);
                float inv0 = 1.0f / rsum8(e0 + e2);
                float inv1 = 1.0f / rsum8(e1 + e3);
                float at0 = e0 * inv0, at1 = e1 * inv1;
                float at2 = e2 * inv0, at3 = e3 * inv1;
                *reinterpret_cast<float2*>(Cf + (size_t)r0 * DM + col) = make_float2(at0, at1);
                *reinterpret_cast<float2*>(Cf + (size_t)r1 * DM + col) = make_float2(at2, at3);
                float2 p0 = __half22float2(*reinterpret_cast<const __half2*>(pe + (size_t)r0 * DM + col));
                float2 p1 = __half22float2(*reinterpret_cast<const __half2*>(pe + (size_t)r1 * DM + col));
                float2 w1 = *reinterpret_cast<const float2*>(vf + (size_t)j1 * KVS + col);
                float2 w2 = *reinterpret_cast<const float2*>(vf + (size_t)j2 * KVS + col);
                float px = at0 * (w1.x + p0.x) + at2 * (w2.x + p1.x);
                float py = at1 * (w1.y + p0.y) + at3 * (w2.y + p1.y);
                px = rsum8(px);
                py = rsum8(py);
                if (gid == 0)
                    *reinterpret_cast<__half2*>(resh + (size_t)n * DM + col) =
                        __floats2half2_rn(px, py);
            }
        }
    }
}

// ---------------- GEN dual GEMM ----------------
#define GEN_SMEM (4 * STG_B + (768 + 256 + 512 + 128) * 4)

__global__ __launch_bounds__(256, 2) void gen_dual_kernel(
    const __half* __restrict__ WT,
    const float* __restrict__ xyz1, const float* __restrict__ xyz2,
    const float* __restrict__ Wd1, const float* __restrict__ bd1,
    const float* __restrict__ bias,
    __half* __restrict__ pe_out, __half* __restrict__ t2_out,
    const float* __restrict__ cc,
    const float* __restrict__ qg, const float* __restrict__ kg,
    const int* __restrict__ knn)
{
    extern __shared__ __align__(16) char smraw[];
    const uint32_t sbase = smem_u32(smraw);

    __half* smA   = (__half*)smraw;
    float*  Fbase = (float*)(smraw + 4 * STG_B);
    float*  smWd1 = Fbase;
    float*  smbd1 = Fbase + 768;
    float*  smrel = Fbase + 1024;
    int*    smknn = (int*)(Fbase + 1536);

    const int tid = threadIdx.x;
    const int bm = blockIdx.y * 128, bn = blockIdx.x * 128;
    const int lane = tid & 31, gid = lane >> 2, tig = lane & 3;
    const int w = tid >> 5, wm = w & 1, wn = w >> 1;
    const int lg = lane >> 3;

    const uint32_t aoff = ((uint32_t)(wm * 64 + (lg & 1) * 8 + (lane & 7)) * SH
                           + (lg >> 1) * 8) * 2;
    const uint32_t boff = ((uint32_t)(wn * 32 + (lg >> 1) * 8 + (lane & 7)) * SH
                           + (lg & 1) * 8) * 2;

    for (int i = tid; i < 768; i += 256) smWd1[i] = Wd1[i];
    smbd1[tid] = bd1[tid & 255];
    if (tid < 128) {
        int j = knn[bm + tid];
        smknn[tid] = j;
        int q = (bm + tid) >> 4;
        smrel[tid * 4 + 0] = xyz1[(size_t)q * 3 + 0] - xyz2[(size_t)j * 3 + 0];
        smrel[tid * 4 + 1] = xyz1[(size_t)q * 3 + 1] - xyz2[(size_t)j * 3 + 1];
        smrel[tid * 4 + 2] = xyz1[(size_t)q * 3 + 2] - xyz2[(size_t)j * 3 + 2];
    }

    float acc[4][4][4];
#pragma unroll
    for (int i = 0; i < 4; i++)
#pragma unroll
        for (int j = 0; j < 4; j++)
#pragma unroll
            for (int r = 0; r < 4; r++) acc[i][j][r] = 0.0f;

    const int Cn = DM / KC;
    const int cprow = tid >> 1;
    const int cpho  = (tid & 1) * 32;

    auto issueB = [&](int c) {
        uint32_t bs = sbase + (uint32_t)(1 + c % NSTAGE) * STG_B;
        const __half* Bg = WT + (size_t)(bn + cprow) * DM + c * KC + cpho;
        uint32_t so = (uint32_t)(cprow * SH + cpho) * 2;
#pragma unroll
        for (int t = 0; t < 4; t++) CP16(bs + so + 16 * t, Bg + 8 * t);
        CP_COMMIT();
    };

    issueB(0);
    issueB(1);
    __syncthreads();

    const int grow = tid >> 1;
    const int gho  = (tid & 1) * 32;
    const float r0v = smrel[grow * 4 + 0];
    const float r1v = smrel[grow * 4 + 1];
    const float r2v = smrel[grow * 4 + 2];

    for (int c = 0; c < Cn; c++) {
        if (c == Cn - 1) cp_wait<0>(); else cp_wait<1>();
        __syncthreads();
        if (c + 2 < Cn) issueB(c + 2);

        {
            __half2 hb[16];
            const int cb = c * KC + gho;
#pragma unroll
            for (int u = 0; u < 16; u++) {
                int ci = cb + u * 2;
                float v0 = fmaf(r0v, smWd1[ci],
                           fmaf(r1v, smWd1[256 + ci],
                           fmaf(r2v, smWd1[512 + ci], smbd1[ci])));
                float v1 = fmaf(r0v, smWd1[ci + 1],
                           fmaf(r1v, smWd1[256 + ci + 1],
                           fmaf(r2v, smWd1[512 + ci + 1], smbd1[ci + 1])));
                hb[u] = __floats2half2_rn(fmaxf(v0, 0.f), fmaxf(v1, 0.f));
            }
            __half* dst = smA + grow * SH + gho;
#pragma unroll
            for (int t = 0; t < 4; t++)
                *reinterpret_cast<uint4*>(dst + 8 * t) = *reinterpret_cast<uint4*>(&hb[4 * t]);
        }
        __syncthreads();

        const uint32_t abase = sbase + aoff;
        const uint32_t bbase = sbase + (uint32_t)(1 + c % NSTAGE) * STG_B + boff;

#pragma unroll
        for (int kk = 0; kk < 4; kk++) {
            uint32_t af[4][4], bf[4][2];
#pragma unroll
            for (int i = 0; i < 4; i++)
                LDSM_X4(af[i][0], af[i][1], af[i][2], af[i][3],
                        abase + i * (16 * SH * 2) + kk * 32);
#pragma unroll
            for (int jp = 0; jp < 2; jp++)
                LDSM_X4(bf[2*jp][0], bf[2*jp][1], bf[2*jp+1][0], bf[2*jp+1][1],
                        bbase + jp * (16 * SH * 2) + kk * 32);
#pragma unroll
            for (int i = 0; i < 4; i++)
#pragma unroll
                for (int j = 0; j < 4; j++)
                    mma_f16(acc[i][j], af[i], bf[j]);
        }
    }

    const int rowbase = bm + wm * 64;
    const int colbase = bn + wn * 32 + tig * 2;
    const bool isPE = (bn < 256);
#pragma unroll
    for (int i = 0; i < 4; i++) {
        int r0 = rowbase + i * 16 + gid;
        int r1 = r0 + 8;
        int n = r0 >> 4;
        int j1 = 0, j2 = 0;
        if (!isPE) { j1 = smknn[r0 - bm]; j2 = smknn[r1 - bm]; }
#pragma unroll
        for (int j = 0; j < 4; j++) {
            int col = colbase + j * 8;
            if (isPE) {
                float2 bb = *reinterpret_cast<const float2*>(bias + col);
                *reinterpret_cast<__half2*>(pe_out + (size_t)r0 * DM + col) =
                    __floats2half2_rn(acc[i][j][0] + bb.x, acc[i][j][1] + bb.y);
                *reinterpret_cast<__half2*>(pe_out + (size_t)r1 * DM + col) =
                    __floats2half2_rn(acc[i][j][2] + bb.x, acc[i][j][3] + bb.y);
            } else {
                int c2 = col - 256;
                float2 ccv = *reinterpret_cast<const float2*>(cc + c2);
                float2 qv  = *reinterpret_cast<const float2*>(qg + (size_t)n * DM + c2);
                float2 k1  = *reinterpret_cast<const float2*>(kg + (size_t)j1 * KVS + c2);
                float2 k2  = *reinterpret_cast<const float2*>(kg + (size_t)j2 * KVS + c2);
                *reinterpret_cast<__half2*>(t2_out + (size_t)r0 * DM + c2) =
                    __floats2half2_rn(fmaxf(acc[i][j][0] + ccv.x + qv.x - k1.x, 0.f),
                                      fmaxf(acc[i][j][1] + ccv.y + qv.y - k1.y, 0.f));
                *reinterpret_cast<__half2*>(t2_out + (size_t)r1 * DM + c2) =
                    __floats2half2_rn(fmaxf(acc[i][j][2] + ccv.x + qv.x - k2.x, 0.f),
                                      fmaxf(acc[i][j][3] + ccv.y + qv.y - k2.y, 0.f));
            }
        }
    }
}

// ---------------- host launch ----------------
template<int MODE, bool OUTH>
static void launch_h(int M, int N, int K,
                     const __half* A, const __half* WT,
                     const float* bias, const float* extra, void* Cout,
                     const __half* pe = nullptr, const float* vf = nullptr,
                     __half* resh = nullptr, const int* knn = nullptr)
{
    cudaFuncSetAttribute(gemm_h<MODE, OUTH>,
                         cudaFuncAttributeMaxDynamicSharedMemorySize, GEMM_SMEM);
    gemm_h<MODE, OUTH><<<dim3(N / 128, M / 128), 256, GEMM_SMEM>>>(
        M, N, K, A, WT, bias, extra, Cout, pe, vf, resh, knn);
}

extern "C" void kernel_launch(void* const* d_in, const int* in_sizes, int n_in,
                              void* d_out, int out_size)
{
    const float* xyz1      = (const float*)d_in[0];
    const float* features1 = (const float*)d_in[1];
    const float* xyz2      = (const float*)d_in[2];
    const float* features2 = (const float*)d_in[3];
    const float* W_fc1     = (const float*)d_in[4];
    const float* b_fc1     = (const float*)d_in[5];
    const float* W_fc2     = (const float*)d_in[6];
    const float* b_fc2     = (const float*)d_in[7];
    const float* Wd1       = (const float*)d_in[8];
    const float* bd1       = (const float*)d_in[9];
    const float* Wd2       = (const float*)d_in[10];
    const float* bd2       = (const float*)d_in[11];
    const float* Wg1       = (const float*)d_in[12];
    const float* bg1       = (const float*)d_in[13];
    const float* Wg2       = (const float*)d_in[14];
    const float* bg2       = (const float*)d_in[15];
    const float* Wq        = (const float*)d_in[16];
    const float* Wk        = (const float*)d_in[17];
    const float* Wv        = (const float*)d_in[18];

    float* out_res  = (float*)d_out;
    float* out_attn = (float*)d_out + (size_t)BN * DP;

    int*    p_knn;  cudaGetSymbolAddress((void**)&p_knn,  g_knn);
    float4* p_sp4;  cudaGetSymbolAddress((void**)&p_sp4,  g_sp4);
    __half* p_f1h;  cudaGetSymbolAddress((void**)&p_f1h,  g_f1h);
    __half* p_f2h;  cudaGetSymbolAddress((void**)&p_f2h,  g_f2h);
    __half* p_x1h;  cudaGetSymbolAddress((void**)&p_x1h,  g_x1h);
    __half* p_x2h;  cudaGetSymbolAddress((void**)&p_x2h,  g_x2h);
    float*  p_qg;   cudaGetSymbolAddress((void**)&p_qg,   g_qg);
    float*  p_kgvf; cudaGetSymbolAddress((void**)&p_kgvf, g_kgvf);
    __half* p_resh; cudaGetSymbolAddress((void**)&p_resh, g_resh);
    __half* p_t2h;  cudaGetSymbolAddress((void**)&p_t2h,  g_t2h);
    __half* p_peh;  cudaGetSymbolAddress((void**)&p_peh,  g_peh);
    __half* w_fc1;  cudaGetSymbolAddress((void**)&w_fc1,  g_wfc1h);
    __half* w_fc2;  cudaGetSymbolAddress((void**)&w_fc2,  g_wfc2h);
    __half* w_dual; cudaGetSymbolAddress((void**)&w_dual, g_wdualh);
    __half* w_g2;   cudaGetSymbolAddress((void**)&w_g2,   g_wg2h);
    __half* w_qg;   cudaGetSymbolAddress((void**)&w_qg,   g_wqgh);
    __half* w_kv;   cudaGetSymbolAddress((void**)&w_kv,   g_wkvh);
    float*  p_cc;   cudaGetSymbolAddress((void**)&p_cc,   g_cc);

    cudaFuncSetAttribute(gen_dual_kernel,
                         cudaFuncAttributeMaxDynamicSharedMemorySize, GEN_SMEM);
    cudaFuncSetAttribute(knn_kernel,
                         cudaFuncAttributeMaxDynamicSharedMemorySize, KNN_SMEM);

    static cudaStream_t sB = nullptr;
    static cudaEvent_t evF = nullptr, evJ = nullptr;
    if (sB == nullptr) {
        cudaStreamCreateWithFlags(&sB, cudaStreamNonBlocking);
        cudaEventCreateWithFlags(&evF, cudaEventDisableTiming);
        cudaEventCreateWithFlags(&evJ, cudaEventDisableTiming);
    }

    dim3 tb(32, 8);

    // ---- fork: stream B runs the ALU-bound KNN branch ----
    cudaEventRecord(evF, 0);
    cudaStreamWaitEvent(sB, evF, 0);
    prep_pts<<<BN / 256, 256, 0, sB>>>(xyz2, p_sp4);
    knn_kernel<<<BN / 32, 256, KNN_SMEM, sB>>>(xyz1, p_sp4, p_knn);
    cudaEventRecord(evJ, sB);

    // ---- stream 0: tensor-bound prep + projection chain ----
    transpose_kernel<<<dim3(DM/32, DP/32), tb>>>(W_fc1, w_fc1, DP, DM);
    f2h_kernel<<<(BN * DP) / 1024, 256>>>(features1, p_f1h);
    f2h_kernel<<<(BN * DP) / 1024, 256>>>(features2, p_f2h);
    transpose_kernel<<<dim3(DM/32, DM/32), tb>>>(Wd2,  w_dual, DM, DM);
    transpose_kernel<<<dim3(DM/32, DM/32), tb>>>(Wg2,  w_g2, DM, DM);
    transpose_kernel<<<dim3(DM/32, DM/32), tb>>>(Wv,   w_kv + DM * DM, DM, DM);
    transpose_kernel<<<dim3(DP/32, DM/32), tb>>>(W_fc2, w_fc2, DM, DP);
    combine_kernel<<<DM, DM>>>(Wq,  Wg1, w_qg);
    combine_kernel<<<DM, DM>>>(Wk,  Wg1, w_kv);
    combine_kernel<<<DM, DM>>>(Wd2, Wg1, w_dual + DM * DM);
    cc_kernel<<<1, DM>>>(bd2, Wg1, bg1, p_cc);

    launch_h<0, true >(BN, DM, DP, p_f1h, w_fc1, b_fc1, nullptr, p_x1h);
    launch_h<0, true >(BN, DM, DP, p_f2h, w_fc1, b_fc1, nullptr, p_x2h);
    launch_h<0, false>(BN, DM, DM, p_x1h, w_qg, nullptr, nullptr, p_qg);
    launch_h<0, false>(BN, KVS, DM, p_x2h, w_kv, nullptr, nullptr, p_kgvf);

    // ---- join: gen_dual needs knn + qg + kgvf ----
    cudaStreamWaitEvent(0, evJ, 0);

    gen_dual_kernel<<<dim3(4, BNK / 128), 256, GEN_SMEM>>>(
        w_dual, xyz1, xyz2, Wd1, bd1, bd2, p_peh, p_t2h, p_cc, p_qg, p_kgvf, p_knn);

    launch_h<2, false>(BNK, DM, DM, p_t2h, w_g2, bg2, nullptr, out_attn,
                       p_peh, p_kgvf + 256, p_resh, p_knn);

    launch_h<0, false>(BN, DP, DM, p_resh, w_fc2, b_fc2, features1, out_res);
}

// round 15
// speedup vs baseline: 1.0905x; 1.0905x over previous
#include <cuda_runtime.h>
#include <cuda_fp16.h>
#include <cstdint>
#include <math.h>

// ---------------- problem constants ----------------
#define BATCH 4
#define NPTS  4096
#define BN    (BATCH*NPTS)          // 16384
#define DP    128
#define DM    256
#define KNN_K 16
#define BNK   (BN*KNN_K)            // 262144
#define INV_SCALE 0.0625f           // 1/sqrt(256)
#define KVS   512                   // row stride of merged kg|vf buffer

// ---------------- device scratch ----------------
__device__ int    g_knn[BNK];                // GLOBAL point index
__device__ float4 g_sp4[BN];                 // xyz2 + norm
__device__ __half g_f1h[BN * DP];
__device__ __half g_f2h[BN * DP];
__device__ __half g_x1h[BN * DM];
__device__ __half g_x2h[BN * DM];
__device__ float  g_qg [BN * DM];            // fp32 (coalesced, L1-friendly)
__device__ __half g_kgvfh[BN * KVS];         // fp16: cols 0-255 kg, 256-511 vf
__device__ __half g_resh[BN * DM];
__device__ __half g_t2h[(size_t)BNK * DM];
__device__ __half g_peh[(size_t)BNK * DM];   // pos_enc fp16
// fp16 weights, [N rows][K cols] K-major
__device__ __half g_wfc1h[DM * DP];
__device__ __half g_wfc2h[DP * DM];
__device__ __half g_wdualh[2 * DM * DM];
__device__ __half g_wg2h [DM * DM];
__device__ __half g_wqgh [DM * DM];
__device__ __half g_wkvh [2 * DM * DM];
__device__ float  g_cc [DM];

// ---------------- PTX helpers ----------------
__device__ __forceinline__ uint32_t smem_u32(const void* p) {
    uint32_t a;
    asm("{ .reg .u64 t; cvta.to.shared.u64 t, %1; cvt.u32.u64 %0, t; }" : "=r"(a) : "l"(p));
    return a;
}
#define CP16(dst, src) \
    asm volatile("cp.async.cg.shared.global [%0], [%1], 16;" :: "r"(dst), "l"(src))
#define CP_COMMIT() asm volatile("cp.async.commit_group;" ::: "memory")
template <int N> __device__ __forceinline__ void cp_wait() {
    asm volatile("cp.async.wait_group %0;" :: "n"(N) : "memory");
}
#define LDSM_X4(r0, r1, r2, r3, addr) \
    asm volatile("ldmatrix.sync.aligned.m8n8.x4.shared.b16 {%0,%1,%2,%3}, [%4];" \
        : "=r"(r0), "=r"(r1), "=r"(r2), "=r"(r3) : "r"(addr))

__device__ __forceinline__ void mma_f16(float* d, const uint32_t* a, const uint32_t* b) {
    asm volatile(
        "mma.sync.aligned.m16n8k16.row.col.f32.f16.f16.f32 "
        "{%0,%1,%2,%3},{%4,%5,%6,%7},{%8,%9},{%0,%1,%2,%3};"
        : "+f"(d[0]), "+f"(d[1]), "+f"(d[2]), "+f"(d[3])
        : "r"(a[0]), "r"(a[1]), "r"(a[2]), "r"(a[3]), "r"(b[0]), "r"(b[1]));
}

__device__ __forceinline__ float rmax8(float v) {
    v = fmaxf(v, __shfl_xor_sync(0xffffffffu, v, 4));
    v = fmaxf(v, __shfl_xor_sync(0xffffffffu, v, 8));
    v = fmaxf(v, __shfl_xor_sync(0xffffffffu, v, 16));
    return v;
}
__device__ __forceinline__ float rsum8(float v) {
    v += __shfl_xor_sync(0xffffffffu, v, 4);
    v += __shfl_xor_sync(0xffffffffu, v, 8);
    v += __shfl_xor_sync(0xffffffffu, v, 16);
    return v;
}

// ---------------- prep kernels ----------------
__global__ void prep_pts(const float* __restrict__ xyz2, float4* __restrict__ sp4)
{
    int i = blockIdx.x * 256 + threadIdx.x;
    float x = xyz2[3*i], y = xyz2[3*i+1], z = xyz2[3*i+2];
    sp4[i] = make_float4(x, y, z, x*x + y*y + z*z);
}

__global__ void f2h_kernel(const float* __restrict__ in, __half* __restrict__ out)
{
    int i = (blockIdx.x * 256 + threadIdx.x) * 4;
    float4 v = *reinterpret_cast<const float4*>(in + i);
    __half2* o = reinterpret_cast<__half2*>(out + i);
    o[0] = __floats2half2_rn(v.x, v.y);
    o[1] = __floats2half2_rn(v.z, v.w);
}

__global__ void transpose_kernel(const float* __restrict__ W, __half* __restrict__ WT,
                                 int K, int N)
{
    __shared__ float t[32][33];
    int bx = blockIdx.x * 32, by = blockIdx.y * 32;
    int tx = threadIdx.x, ty = threadIdx.y;
#pragma unroll
    for (int i = 0; i < 32; i += 8)
        t[ty + i][tx] = W[(size_t)(by + ty + i) * N + bx + tx];
    __syncthreads();
#pragma unroll
    for (int i = 0; i < 32; i += 8)
        WT[(size_t)(bx + ty + i) * K + by + tx] = __float2half(t[tx][ty + i]);
}

__global__ void combine_kernel(const float* __restrict__ W1, const float* __restrict__ W2,
                               __half* __restrict__ outT)
{
    __shared__ float colv[DM];
    int n = blockIdx.x, k = threadIdx.x;
    colv[k] = W2[k * DM + n];
    __syncthreads();
    const float* w = W1 + k * DM;
    float s = 0.0f;
#pragma unroll 8
    for (int m = 0; m < DM; m++) s = fmaf(w[m], colv[m], s);
    outT[n * DM + k] = __float2half(s);
}

__global__ void cc_kernel(const float* __restrict__ bd2, const float* __restrict__ Wg1,
                          const float* __restrict__ bg1, float* __restrict__ cc)
{
    int n = threadIdx.x;
    float s = bg1[n];
#pragma unroll 8
    for (int m = 0; m < DM; m++) s = fmaf(bd2[m], Wg1[m * DM + n], s);
    cc[n] = s;
}

// ---------------- KNN: register ladder, 4 threads/query, smem merge (round-13) ----------------
#define KNN_SMEM (2 * 4 * 33 * 64 * 4)

__global__ __launch_bounds__(256) void knn_kernel(
    const float* __restrict__ xyz1, const float4* __restrict__ sp4g,
    int* __restrict__ knn)
{
    extern __shared__ __align__(16) float ks[];
    float* sd = ks;                       // [sub][k][ql]
    int*   si = (int*)(ks + 4 * 33 * 64);

    const int tid = threadIdx.x;
    const int l = tid & 31, w = tid >> 5;
    const int sub = w & 3, qgrp = w >> 2;
    const int ql = qgrp * 32 + l;         // 0..63
    const int qg = blockIdx.x * 64 + ql;  // global query
    const int b  = qg >> 12;

    const float qx = xyz1[3*qg], qy = xyz1[3*qg+1], qz = xyz1[3*qg+2];
    const float qn = qx*qx + qy*qy + qz*qz;

    float bd[32]; int bi[32];
#pragma unroll
    for (int i = 0; i < 32; i++) { bd[i] = 3.4e38f; bi[i] = 0; }

    const float4* sp = sp4g + b * NPTS + sub * 1024;
    const int jbase = sub * 1024;
    for (int t = 0; t < 1024; t++) {
        float4 c = __ldg(sp + t);
        float d = qn + c.w - 2.0f * (qx*c.x + qy*c.y + qz*c.z);
        if (d < bd[31]) {                 // strict < : stable tie order
            int j = jbase + t;
            bool pr = true;
#pragma unroll
            for (int p = 31; p > 0; p--) {
                bool sh = d < bd[p-1];
                float vv = sh ? bd[p-1] : d;
                int   ii = sh ? bi[p-1] : j;
                if (pr) { bd[p] = vv; bi[p] = ii; }
                pr = sh;
            }
            if (pr) { bd[0] = d; bi[0] = j; }
        }
    }

#pragma unroll
    for (int k = 0; k < 32; k++) {
        sd[(sub * 33 + k) * 64 + ql] = bd[k];
        si[(sub * 33 + k) * 64 + ql] = bi[k];
    }
    sd[(sub * 33 + 32) * 64 + ql] = 3.4e38f;       // sentinel
    si[(sub * 33 + 32) * 64 + ql] = 0x7fffffff;
    __syncthreads();

    if (tid < 64) {
        const int q = tid;
        const int qgl = blockIdx.x * 64 + q;
        const int base = (qgl >> 12) * NPTS;
        int c0 = 0, c1 = 0, c2 = 0, c3 = 0;
        float d0 = sd[(0*33)*64+q], d1 = sd[(1*33)*64+q],
              d2 = sd[(2*33)*64+q], d3 = sd[(3*33)*64+q];
        int   i0 = si[(0*33)*64+q], i1 = si[(1*33)*64+q],
              i2 = si[(2*33)*64+q], i3 = si[(3*33)*64+q];
        int* o = knn + (size_t)qgl * KNN_K;
#pragma unroll 1
        for (int r = 0; r < 32; r++) {
            float bdv = d0; int biv = i0; int sel = 0;
            if (d1 < bdv || (d1 == bdv && i1 < biv)) { bdv = d1; biv = i1; sel = 1; }
            if (d2 < bdv || (d2 == bdv && i2 < biv)) { bdv = d2; biv = i2; sel = 2; }
            if (d3 < bdv || (d3 == bdv && i3 < biv)) { bdv = d3; biv = i3; sel = 3; }
            if (!(r & 1)) o[r >> 1] = base + biv;   // even ranks only
            if (sel == 0)      { c0++; d0 = sd[(0*33+c0)*64+q]; i0 = si[(0*33+c0)*64+q]; }
            else if (sel == 1) { c1++; d1 = sd[(1*33+c1)*64+q]; i1 = si[(1*33+c1)*64+q]; }
            else if (sel == 2) { c2++; d2 = sd[(2*33+c2)*64+q]; i2 = si[(2*33+c2)*64+q]; }
            else               { c3++; d3 = sd[(3*33+c3)*64+q]; i3 = si[(3*33+c3)*64+q]; }
        }
    }
}

// ---------------- fp16 GEMM config ----------------
#define KC 64
#define SH 72
#define STG_B 18432
#define NSTAGE 3
#define GEMM_SMEM (NSTAGE * 2 * STG_B)

template<int MODE, bool OUTH>
__global__ __launch_bounds__(256, 2) void gemm_h(
    int M, int N, int K,
    const __half* __restrict__ A, const __half* __restrict__ WT,
    const float* __restrict__ bias, const float* __restrict__ extra,
    void* __restrict__ Cout,
    const __half* __restrict__ pe, const __half* __restrict__ vf,
    __half* __restrict__ resh, const int* __restrict__ knn)
{
    extern __shared__ __align__(16) char smraw[];
    const uint32_t sbase = smem_u32(smraw);

    const int tid = threadIdx.x;
    const int bm = blockIdx.y * 128, bn = blockIdx.x * 128;
    const int lane = tid & 31, gid = lane >> 2, tig = lane & 3;
    const int w = tid >> 5, wm = w & 1, wn = w >> 1;
    const int lg = lane >> 3;

    const uint32_t aoff = ((uint32_t)(wm * 64 + (lg & 1) * 8 + (lane & 7)) * SH
                           + (lg >> 1) * 8) * 2;
    const uint32_t boff = ((uint32_t)(wn * 32 + (lg >> 1) * 8 + (lane & 7)) * SH
                           + (lg & 1) * 8) * 2;

    float acc[4][4][4];
#pragma unroll
    for (int i = 0; i < 4; i++)
#pragma unroll
        for (int j = 0; j < 4; j++)
#pragma unroll
            for (int r = 0; r < 4; r++) acc[i][j][r] = 0.0f;

    const int Cn = K / KC;
    const int cprow = tid >> 1;
    const int cpho  = (tid & 1) * 32;

    auto issue = [&](int c) {
        uint32_t st = sbase + (uint32_t)(c % NSTAGE) * (2 * STG_B);
        uint32_t bs = st + STG_B;
        const __half* Ag = A  + (size_t)(bm + cprow) * K + c * KC + cpho;
        const __half* Bg = WT + (size_t)(bn + cprow) * K + c * KC + cpho;
        uint32_t so = (uint32_t)(cprow * SH + cpho) * 2;
#pragma unroll
        for (int t = 0; t < 4; t++) {
            CP16(st + so + 16 * t, Ag + 8 * t);
            CP16(bs + so + 16 * t, Bg + 8 * t);
        }
        CP_COMMIT();
    };

    issue(0);
    issue(1);
    for (int c = 0; c < Cn; c++) {
        if (c == Cn - 1) cp_wait<0>(); else cp_wait<1>();
        __syncthreads();
        if (c + 2 < Cn) issue(c + 2);

        const uint32_t abase = sbase + (uint32_t)(c % NSTAGE) * (2 * STG_B) + aoff;
        const uint32_t bbase = sbase + (uint32_t)(c % NSTAGE) * (2 * STG_B) + STG_B + boff;

#pragma unroll
        for (int kk = 0; kk < 4; kk++) {
            uint32_t af[4][4], bf[4][2];
#pragma unroll
            for (int i = 0; i < 4; i++)
                LDSM_X4(af[i][0], af[i][1], af[i][2], af[i][3],
                        abase + i * (16 * SH * 2) + kk * 32);
#pragma unroll
            for (int jp = 0; jp < 2; jp++)
                LDSM_X4(bf[2*jp][0], bf[2*jp][1], bf[2*jp+1][0], bf[2*jp+1][1],
                        bbase + jp * (16 * SH * 2) + kk * 32);
#pragma unroll
            for (int i = 0; i < 4; i++)
#pragma unroll
                for (int j = 0; j < 4; j++)
                    mma_f16(acc[i][j], af[i], bf[j]);
        }
    }

    const int rowbase = bm + wm * 64;
    const int colbase = bn + wn * 32 + tig * 2;

    if constexpr (MODE == 0) {
#pragma unroll
        for (int i = 0; i < 4; i++) {
            int r0 = rowbase + i * 16 + gid;
#pragma unroll
            for (int j = 0; j < 4; j++) {
                int col = colbase + j * 8;
                float2 v0 = make_float2(acc[i][j][0], acc[i][j][1]);
                float2 v1 = make_float2(acc[i][j][2], acc[i][j][3]);
                if (bias) {
                    float2 bb = *reinterpret_cast<const float2*>(bias + col);
                    v0.x += bb.x; v0.y += bb.y; v1.x += bb.x; v1.y += bb.y;
                }
                if (extra) {
                    float2 e0 = *reinterpret_cast<const float2*>(extra + (size_t)r0 * N + col);
                    float2 e1 = *reinterpret_cast<const float2*>(extra + (size_t)(r0 + 8) * N + col);
                    v0.x += e0.x; v0.y += e0.y; v1.x += e1.x; v1.y += e1.y;
                }
                if (OUTH) {
                    __half* Ch = (__half*)Cout;
                    *reinterpret_cast<__half2*>(Ch + (size_t)r0 * N + col) = __floats2half2_rn(v0.x, v0.y);
                    *reinterpret_cast<__half2*>(Ch + (size_t)(r0 + 8) * N + col) = __floats2half2_rn(v1.x, v1.y);
                } else {
                    float* Cf = (float*)Cout;
                    *reinterpret_cast<float2*>(Cf + (size_t)r0 * N + col) = v0;
                    *reinterpret_cast<float2*>(Cf + (size_t)(r0 + 8) * N + col) = v1;
                }
            }
        }
    } else {  // MODE 2: vf fp16 at stride KVS
        float* Cf = (float*)Cout;
#pragma unroll
        for (int i = 0; i < 4; i++) {
            int r0 = rowbase + i * 16 + gid;
            int r1 = r0 + 8;
            int n = r0 >> 4;
            int j1 = knn[r0], j2 = knn[r1];
#pragma unroll
            for (int j = 0; j < 4; j++) {
                int col = colbase + j * 8;
                float2 bb = *reinterpret_cast<const float2*>(bias + col);
                float a0 = acc[i][j][0] + bb.x;
                float a1 = acc[i][j][1] + bb.y;
                float a2 = acc[i][j][2] + bb.x;
                float a3 = acc[i][j][3] + bb.y;
                float m0 = rmax8(fmaxf(a0, a2));
                float m1 = rmax8(fmaxf(a1, a3));
                float e0 = __expf((a0 - m0) * INV_SCALE);
                float e1 = __expf((a1 - m1) * INV_SCALE);
                float e2 = __expf((a2 - m0) * INV_SCALE);
                float e3 = __expf((a3 - m1) * INV_SCALE);
                float inv0 = 1.0f / rsum8(e0 + e2);
                float inv1 = 1.0f / rsum8(e1 + e3);
                float at0 = e0 * inv0, at1 = e1 * inv1;
                float at2 = e2 * inv0, at3 = e3 * inv1;
                *reinterpret_cast<float2*>(Cf + (size_t)r0 * DM + col) = make_float2(at0, at1);
                *reinterpret_cast<float2*>(Cf + (size_t)r1 * DM + col) = make_float2(at2, at3);
                float2 p0 = __half22float2(*reinterpret_cast<const __half2*>(pe + (size_t)r0 * DM + col));
                float2 p1 = __half22float2(*reinterpret_cast<const __half2*>(pe + (size_t)r1 * DM + col));
                float2 w1 = __half22float2(*reinterpret_cast<const __half2*>(vf + (size_t)j1 * KVS + col));
                float2 w2 = __half22float2(*reinterpret_cast<const __half2*>(vf + (size_t)j2 * KVS + col));
                float px = at0 * (w1.x + p0.x) + at2 * (w2.x + p1.x);
                float py = at1 * (w1.y + p0.y) + at3 * (w2.y + p1.y);
                px = rsum8(px);
                py = rsum8(py);
                if (gid == 0)
                    *reinterpret_cast<__half2*>(resh + (size_t)n * DM + col) =
                        __floats2half2_rn(px, py);
            }
        }
    }
}

// ---------------- GEN dual GEMM ----------------
#define GEN_SMEM (4 * STG_B + (768 + 256 + 512 + 128) * 4)

__global__ __launch_bounds__(256, 2) void gen_dual_kernel(
    const __half* __restrict__ WT,
    const float* __restrict__ xyz1, const float* __restrict__ xyz2,
    const float* __restrict__ Wd1, const float* __restrict__ bd1,
    const float* __restrict__ bias,
    __half* __restrict__ pe_out, __half* __restrict__ t2_out,
    const float* __restrict__ cc,
    const float* __restrict__ qg, const __half* __restrict__ kg,  // kg fp16, stride KVS
    const int* __restrict__ knn)
{
    extern __shared__ __align__(16) char smraw[];
    const uint32_t sbase = smem_u32(smraw);

    __half* smA   = (__half*)smraw;
    float*  Fbase = (float*)(smraw + 4 * STG_B);
    float*  smWd1 = Fbase;
    float*  smbd1 = Fbase + 768;
    float*  smrel = Fbase + 1024;
    int*    smknn = (int*)(Fbase + 1536);

    const int tid = threadIdx.x;
    const int bm = blockIdx.y * 128, bn = blockIdx.x * 128;
    const int lane = tid & 31, gid = lane >> 2, tig = lane & 3;
    const int w = tid >> 5, wm = w & 1, wn = w >> 1;
    const int lg = lane >> 3;

    const uint32_t aoff = ((uint32_t)(wm * 64 + (lg & 1) * 8 + (lane & 7)) * SH
                           + (lg >> 1) * 8) * 2;
    const uint32_t boff = ((uint32_t)(wn * 32 + (lg >> 1) * 8 + (lane & 7)) * SH
                           + (lg & 1) * 8) * 2;

    for (int i = tid; i < 768; i += 256) smWd1[i] = Wd1[i];
    smbd1[tid] = bd1[tid & 255];
    if (tid < 128) {
        int j = knn[bm + tid];
        smknn[tid] = j;
        int q = (bm + tid) >> 4;
        smrel[tid * 4 + 0] = xyz1[(size_t)q * 3 + 0] - xyz2[(size_t)j * 3 + 0];
        smrel[tid * 4 + 1] = xyz1[(size_t)q * 3 + 1] - xyz2[(size_t)j * 3 + 1];
        smrel[tid * 4 + 2] = xyz1[(size_t)q * 3 + 2] - xyz2[(size_t)j * 3 + 2];
    }

    float acc[4][4][4];
#pragma unroll
    for (int i = 0; i < 4; i++)
#pragma unroll
        for (int j = 0; j < 4; j++)
#pragma unroll
            for (int r = 0; r < 4; r++) acc[i][j][r] = 0.0f;

    const int Cn = DM / KC;
    const int cprow = tid >> 1;
    const int cpho  = (tid & 1) * 32;

    auto issueB = [&](int c) {
        uint32_t bs = sbase + (uint32_t)(1 + c % NSTAGE) * STG_B;
        const __half* Bg = WT + (size_t)(bn + cprow) * DM + c * KC + cpho;
        uint32_t so = (uint32_t)(cprow * SH + cpho) * 2;
#pragma unroll
        for (int t = 0; t < 4; t++) CP16(bs + so + 16 * t, Bg + 8 * t);
        CP_COMMIT();
    };

    issueB(0);
    issueB(1);
    __syncthreads();

    const int grow = tid >> 1;
    const int gho  = (tid & 1) * 32;
    const float r0v = smrel[grow * 4 + 0];
    const float r1v = smrel[grow * 4 + 1];
    const float r2v = smrel[grow * 4 + 2];

    for (int c = 0; c < Cn; c++) {
        if (c == Cn - 1) cp_wait<0>(); else cp_wait<1>();
        __syncthreads();
        if (c + 2 < Cn) issueB(c + 2);

        {
            __half2 hb[16];
            const int cb = c * KC + gho;
#pragma unroll
            for (int u = 0; u < 16; u++) {
                int ci = cb + u * 2;
                float v0 = fmaf(r0v, smWd1[ci],
                           fmaf(r1v, smWd1[256 + ci],
                           fmaf(r2v, smWd1[512 + ci], smbd1[ci])));
                float v1 = fmaf(r0v, smWd1[ci + 1],
                           fmaf(r1v, smWd1[256 + ci + 1],
                           fmaf(r2v, smWd1[512 + ci + 1], smbd1[ci + 1])));
                hb[u] = __floats2half2_rn(fmaxf(v0, 0.f), fmaxf(v1, 0.f));
            }
            __half* dst = smA + grow * SH + gho;
#pragma unroll
            for (int t = 0; t < 4; t++)
                *reinterpret_cast<uint4*>(dst + 8 * t) = *reinterpret_cast<uint4*>(&hb[4 * t]);
        }
        __syncthreads();

        const uint32_t abase = sbase + aoff;
        const uint32_t bbase = sbase + (uint32_t)(1 + c % NSTAGE) * STG_B + boff;

#pragma unroll
        for (int kk = 0; kk < 4; kk++) {
            uint32_t af[4][4], bf[4][2];
#pragma unroll
            for (int i = 0; i < 4; i++)
                LDSM_X4(af[i][0], af[i][1], af[i][2], af[i][3],
                        abase + i * (16 * SH * 2) + kk * 32);
#pragma unroll
            for (int jp = 0; jp < 2; jp++)
                LDSM_X4(bf[2*jp][0], bf[2*jp][1], bf[2*jp+1][0], bf[2*jp+1][1],
                        bbase + jp * (16 * SH * 2) + kk * 32);
#pragma unroll
            for (int i = 0; i < 4; i++)
#pragma unroll
                for (int j = 0; j < 4; j++)
                    mma_f16(acc[i][j], af[i], bf[j]);
        }
    }

    const int rowbase = bm + wm * 64;
    const int colbase = bn + wn * 32 + tig * 2;
    const bool isPE = (bn < 256);
#pragma unroll
    for (int i = 0; i < 4; i++) {
        int r0 = rowbase + i * 16 + gid;
        int r1 = r0 + 8;
        int n = r0 >> 4;
        int j1 = 0, j2 = 0;
        if (!isPE) { j1 = smknn[r0 - bm]; j2 = smknn[r1 - bm]; }
#pragma unroll
        for (int j = 0; j < 4; j++) {
            int col = colbase + j * 8;
            if (isPE) {
                float2 bb = *reinterpret_cast<const float2*>(bias + col);
                *reinterpret_cast<__half2*>(pe_out + (size_t)r0 * DM + col) =
                    __floats2half2_rn(acc[i][j][0] + bb.x, acc[i][j][1] + bb.y);
                *reinterpret_cast<__half2*>(pe_out + (size_t)r1 * DM + col) =
                    __floats2half2_rn(acc[i][j][2] + bb.x, acc[i][j][3] + bb.y);
            } else {
                int c2 = col - 256;
                float2 ccv = *reinterpret_cast<const float2*>(cc + c2);
                float2 qv  = *reinterpret_cast<const float2*>(qg + (size_t)n * DM + c2);
                float2 k1  = __half22float2(*reinterpret_cast<const __half2*>(kg + (size_t)j1 * KVS + c2));
                float2 k2  = __half22float2(*reinterpret_cast<const __half2*>(kg + (size_t)j2 * KVS + c2));
                *reinterpret_cast<__half2*>(t2_out + (size_t)r0 * DM + c2) =
                    __floats2half2_rn(fmaxf(acc[i][j][0] + ccv.x + qv.x - k1.x, 0.f),
                                      fmaxf(acc[i][j][1] + ccv.y + qv.y - k1.y, 0.f));
                *reinterpret_cast<__half2*>(t2_out + (size_t)r1 * DM + c2) =
                    __floats2half2_rn(fmaxf(acc[i][j][2] + ccv.x + qv.x - k2.x, 0.f),
                                      fmaxf(acc[i][j][3] + ccv.y + qv.y - k2.y, 0.f));
            }
        }
    }
}

// ---------------- host launch ----------------
template<int MODE, bool OUTH>
static void launch_h(int M, int N, int K,
                     const __half* A, const __half* WT,
                     const float* bias, const float* extra, void* Cout,
                     const __half* pe = nullptr, const __half* vf = nullptr,
                     __half* resh = nullptr, const int* knn = nullptr)
{
    cudaFuncSetAttribute(gemm_h<MODE, OUTH>,
                         cudaFuncAttributeMaxDynamicSharedMemorySize, GEMM_SMEM);
    gemm_h<MODE, OUTH><<<dim3(N / 128, M / 128), 256, GEMM_SMEM>>>(
        M, N, K, A, WT, bias, extra, Cout, pe, vf, resh, knn);
}

extern "C" void kernel_launch(void* const* d_in, const int* in_sizes, int n_in,
                              void* d_out, int out_size)
{
    const float* xyz1      = (const float*)d_in[0];
    const float* features1 = (const float*)d_in[1];
    const float* xyz2      = (const float*)d_in[2];
    const float* features2 = (const float*)d_in[3];
    const float* W_fc1     = (const float*)d_in[4];
    const float* b_fc1     = (const float*)d_in[5];
    const float* W_fc2     = (const float*)d_in[6];
    const float* b_fc2     = (const float*)d_in[7];
    const float* Wd1       = (const float*)d_in[8];
    const float* bd1       = (const float*)d_in[9];
    const float* Wd2       = (const float*)d_in[10];
    const float* bd2       = (const float*)d_in[11];
    const float* Wg1       = (const float*)d_in[12];
    const float* bg1       = (const float*)d_in[13];
    const float* Wg2       = (const float*)d_in[14];
    const float* bg2       = (const float*)d_in[15];
    const float* Wq        = (const float*)d_in[16];
    const float* Wk        = (const float*)d_in[17];
    const float* Wv        = (const float*)d_in[18];

    float* out_res  = (float*)d_out;
    float* out_attn = (float*)d_out + (size_t)BN * DP;

    int*    p_knn;  cudaGetSymbolAddress((void**)&p_knn,  g_knn);
    float4* p_sp4;  cudaGetSymbolAddress((void**)&p_sp4,  g_sp4);
    __half* p_f1h;  cudaGetSymbolAddress((void**)&p_f1h,  g_f1h);
    __half* p_f2h;  cudaGetSymbolAddress((void**)&p_f2h,  g_f2h);
    __half* p_x1h;  cudaGetSymbolAddress((void**)&p_x1h,  g_x1h);
    __half* p_x2h;  cudaGetSymbolAddress((void**)&p_x2h,  g_x2h);
    float*  p_qg;   cudaGetSymbolAddress((void**)&p_qg,   g_qg);
    __half* p_kgvf; cudaGetSymbolAddress((void**)&p_kgvf, g_kgvfh);
    __half* p_resh; cudaGetSymbolAddress((void**)&p_resh, g_resh);
    __half* p_t2h;  cudaGetSymbolAddress((void**)&p_t2h,  g_t2h);
    __half* p_peh;  cudaGetSymbolAddress((void**)&p_peh,  g_peh);
    __half* w_fc1;  cudaGetSymbolAddress((void**)&w_fc1,  g_wfc1h);
    __half* w_fc2;  cudaGetSymbolAddress((void**)&w_fc2,  g_wfc2h);
    __half* w_dual; cudaGetSymbolAddress((void**)&w_dual, g_wdualh);
    __half* w_g2;   cudaGetSymbolAddress((void**)&w_g2,   g_wg2h);
    __half* w_qg;   cudaGetSymbolAddress((void**)&w_qg,   g_wqgh);
    __half* w_kv;   cudaGetSymbolAddress((void**)&w_kv,   g_wkvh);
    float*  p_cc;   cudaGetSymbolAddress((void**)&p_cc,   g_cc);

    cudaFuncSetAttribute(gen_dual_kernel,
                         cudaFuncAttributeMaxDynamicSharedMemorySize, GEN_SMEM);
    cudaFuncSetAttribute(knn_kernel,
                         cudaFuncAttributeMaxDynamicSharedMemorySize, KNN_SMEM);

    static cudaStream_t sB = nullptr;
    static cudaEvent_t evF = nullptr, evJ = nullptr;
    if (sB == nullptr) {
        cudaStreamCreateWithFlags(&sB, cudaStreamNonBlocking);
        cudaEventCreateWithFlags(&evF, cudaEventDisableTiming);
        cudaEventCreateWithFlags(&evJ, cudaEventDisableTiming);
    }

    dim3 tb(32, 8);

    // ---- fork: stream B runs the ALU-bound KNN branch ----
    cudaEventRecord(evF, 0);
    cudaStreamWaitEvent(sB, evF, 0);
    prep_pts<<<BN / 256, 256, 0, sB>>>(xyz2, p_sp4);
    knn_kernel<<<BN / 64, 256, KNN_SMEM, sB>>>(xyz1, p_sp4, p_knn);
    cudaEventRecord(evJ, sB);

    // ---- stream 0: tensor-bound prep + projection chain ----
    transpose_kernel<<<dim3(DM/32, DP/32), tb>>>(W_fc1, w_fc1, DP, DM);
    f2h_kernel<<<(BN * DP) / 1024, 256>>>(features1, p_f1h);
    f2h_kernel<<<(BN * DP) / 1024, 256>>>(features2, p_f2h);
    transpose_kernel<<<dim3(DM/32, DM/32), tb>>>(Wd2,  w_dual, DM, DM);
    transpose_kernel<<<dim3(DM/32, DM/32), tb>>>(Wg2,  w_g2, DM, DM);
    transpose_kernel<<<dim3(DM/32, DM/32), tb>>>(Wv,   w_kv + DM * DM, DM, DM);
    transpose_kernel<<<dim3(DP/32, DM/32), tb>>>(W_fc2, w_fc2, DM, DP);
    combine_kernel<<<DM, DM>>>(Wq,  Wg1, w_qg);
    combine_kernel<<<DM, DM>>>(Wk,  Wg1, w_kv);
    combine_kernel<<<DM, DM>>>(Wd2, Wg1, w_dual + DM * DM);
    cc_kernel<<<1, DM>>>(bd2, Wg1, bg1, p_cc);

    launch_h<0, true >(BN, DM, DP, p_f1h, w_fc1, b_fc1, nullptr, p_x1h);
    launch_h<0, true >(BN, DM, DP, p_f2h, w_fc1, b_fc1, nullptr, p_x2h);
    launch_h<0, false>(BN, DM, DM, p_x1h, w_qg, nullptr, nullptr, p_qg);
    launch_h<0, true >(BN, KVS, DM, p_x2h, w_kv, nullptr, nullptr, p_kgvf);

    // ---- join: gen_dual needs knn + qg + kgvf ----
    cudaStreamWaitEvent(0, evJ, 0);

    gen_dual_kernel<<<dim3(4, BNK / 128), 256, GEN_SMEM>>>(
        w_dual, xyz1, xyz2, Wd1, bd1, bd2, p_peh, p_t2h, p_cc, p_qg, p_kgvf, p_knn);

    launch_h<2, false>(BNK, DM, DM, p_t2h, w_g2, bg2, nullptr, out_attn,
                       p_peh, p_kgvf + 256, p_resh, p_knn);

    launch_h<0, false>(BN, DP, DM, p_resh, w_fc2, b_fc2, features1, out_res);
}

// round 16
// speedup vs baseline: 1.1079x; 1.0160x over previous
#include <cuda_runtime.h>
#include <cuda_fp16.h>
#include <cstdint>
#include <math.h>

// ---------------- problem constants ----------------
#define BATCH 4
#define NPTS  4096
#define BN    (BATCH*NPTS)          // 16384
#define DP    128
#define DM    256
#define KNN_K 16
#define BNK   (BN*KNN_K)            // 262144
#define INV_SCALE 0.0625f           // 1/sqrt(256)
#define KVS   512                   // row stride of merged kg|vf buffer

// ---------------- device scratch ----------------
__device__ int    g_knn[BNK];                // GLOBAL point index
__device__ float4 g_sp4[BN];                 // xyz2 + norm
__device__ __half g_f1h[BN * DP];
__device__ __half g_f2h[BN * DP];
__device__ __half g_x1h[BN * DM];
__device__ __half g_x2h[BN * DM];
__device__ float  g_qg [BN * DM];
__device__ __half g_kgvfh[BN * KVS];         // fp16: cols 0-255 kg, 256-511 vf
__device__ __half g_resh[BN * DM];
__device__ __half g_t2h[(size_t)BNK * DM];
__device__ __half g_peh[(size_t)BNK * DM];   // pos_enc fp16
// fp16 weights, [N rows][K cols] K-major
__device__ __half g_wfc1h[DM * DP];
__device__ __half g_wfc2h[DP * DM];
__device__ __half g_wdualh[2 * DM * DM];
__device__ __half g_wg2h [DM * DM];
__device__ __half g_wqgh [DM * DM];
__device__ __half g_wkvh [2 * DM * DM];
__device__ float  g_cc [DM];

// ---------------- PTX helpers ----------------
__device__ __forceinline__ uint32_t smem_u32(const void* p) {
    uint32_t a;
    asm("{ .reg .u64 t; cvta.to.shared.u64 t, %1; cvt.u32.u64 %0, t; }" : "=r"(a) : "l"(p));
    return a;
}
#define CP16(dst, src) \
    asm volatile("cp.async.cg.shared.global [%0], [%1], 16;" :: "r"(dst), "l"(src))
#define CP_COMMIT() asm volatile("cp.async.commit_group;" ::: "memory")
template <int N> __device__ __forceinline__ void cp_wait() {
    asm volatile("cp.async.wait_group %0;" :: "n"(N) : "memory");
}
#define LDSM_X4(r0, r1, r2, r3, addr) \
    asm volatile("ldmatrix.sync.aligned.m8n8.x4.shared.b16 {%0,%1,%2,%3}, [%4];" \
        : "=r"(r0), "=r"(r1), "=r"(r2), "=r"(r3) : "r"(addr))

__device__ __forceinline__ void mma_f16(float* d, const uint32_t* a, const uint32_t* b) {
    asm volatile(
        "mma.sync.aligned.m16n8k16.row.col.f32.f16.f16.f32 "
        "{%0,%1,%2,%3},{%4,%5,%6,%7},{%8,%9},{%0,%1,%2,%3};"
        : "+f"(d[0]), "+f"(d[1]), "+f"(d[2]), "+f"(d[3])
        : "r"(a[0]), "r"(a[1]), "r"(a[2]), "r"(a[3]), "r"(b[0]), "r"(b[1]));
}

__device__ __forceinline__ float rmax8(float v) {
    v = fmaxf(v, __shfl_xor_sync(0xffffffffu, v, 4));
    v = fmaxf(v, __shfl_xor_sync(0xffffffffu, v, 8));
    v = fmaxf(v, __shfl_xor_sync(0xffffffffu, v, 16));
    return v;
}
__device__ __forceinline__ float rsum8(float v) {
    v += __shfl_xor_sync(0xffffffffu, v, 4);
    v += __shfl_xor_sync(0xffffffffu, v, 8);
    v += __shfl_xor_sync(0xffffffffu, v, 16);
    return v;
}

// ---------------- prep kernels ----------------
__global__ void prep_pts(const float* __restrict__ xyz2, float4* __restrict__ sp4)
{
    int i = blockIdx.x * 256 + threadIdx.x;
    float x = xyz2[3*i], y = xyz2[3*i+1], z = xyz2[3*i+2];
    sp4[i] = make_float4(x, y, z, x*x + y*y + z*z);
}

__global__ void f2h_kernel(const float* __restrict__ in, __half* __restrict__ out)
{
    int i = (blockIdx.x * 256 + threadIdx.x) * 4;
    float4 v = *reinterpret_cast<const float4*>(in + i);
    __half2* o = reinterpret_cast<__half2*>(out + i);
    o[0] = __floats2half2_rn(v.x, v.y);
    o[1] = __floats2half2_rn(v.z, v.w);
}

__global__ void transpose_kernel(const float* __restrict__ W, __half* __restrict__ WT,
                                 int K, int N)
{
    __shared__ float t[32][33];
    int bx = blockIdx.x * 32, by = blockIdx.y * 32;
    int tx = threadIdx.x, ty = threadIdx.y;
#pragma unroll
    for (int i = 0; i < 32; i += 8)
        t[ty + i][tx] = W[(size_t)(by + ty + i) * N + bx + tx];
    __syncthreads();
#pragma unroll
    for (int i = 0; i < 32; i += 8)
        WT[(size_t)(bx + ty + i) * K + by + tx] = __float2half(t[tx][ty + i]);
}

__global__ void combine_kernel(const float* __restrict__ W1, const float* __restrict__ W2,
                               __half* __restrict__ outT)
{
    __shared__ float colv[DM];
    int n = blockIdx.x, k = threadIdx.x;
    colv[k] = W2[k * DM + n];
    __syncthreads();
    const float* w = W1 + k * DM;
    float s = 0.0f;
#pragma unroll 8
    for (int m = 0; m < DM; m++) s = fmaf(w[m], colv[m], s);
    outT[n * DM + k] = __float2half(s);
}

__global__ void cc_kernel(const float* __restrict__ bd2, const float* __restrict__ Wg1,
                          const float* __restrict__ bg1, float* __restrict__ cc)
{
    int n = threadIdx.x;
    float s = bg1[n];
#pragma unroll 8
    for (int m = 0; m < DM; m++) s = fmaf(bd2[m], Wg1[m * DM + n], s);
    cc[n] = s;
}

// ---------------- KNN: register ladder, 4 threads/query, smem merge ----------------
#define KNN_SMEM (2 * 4 * 33 * 64 * 4)

__global__ __launch_bounds__(256) void knn_kernel(
    const float* __restrict__ xyz1, const float4* __restrict__ sp4g,
    int* __restrict__ knn)
{
    extern __shared__ __align__(16) float ks[];
    float* sd = ks;                       // [sub][k][ql]
    int*   si = (int*)(ks + 4 * 33 * 64);

    const int tid = threadIdx.x;
    const int l = tid & 31, w = tid >> 5;
    const int sub = w & 3, qgrp = w >> 2;
    const int ql = qgrp * 32 + l;
    const int qg = blockIdx.x * 64 + ql;
    const int b  = qg >> 12;

    const float qx = xyz1[3*qg], qy = xyz1[3*qg+1], qz = xyz1[3*qg+2];
    const float qn = qx*qx + qy*qy + qz*qz;

    float bd[32]; int bi[32];
#pragma unroll
    for (int i = 0; i < 32; i++) { bd[i] = 3.4e38f; bi[i] = 0; }

    const float4* sp = sp4g + b * NPTS + sub * 1024;
    const int jbase = sub * 1024;
    for (int t = 0; t < 1024; t++) {
        float4 c = __ldg(sp + t);
        float d = qn + c.w - 2.0f * (qx*c.x + qy*c.y + qz*c.z);
        if (d < bd[31]) {
            int j = jbase + t;
            bool pr = true;
#pragma unroll
            for (int p = 31; p > 0; p--) {
                bool sh = d < bd[p-1];
                float vv = sh ? bd[p-1] : d;
                int   ii = sh ? bi[p-1] : j;
                if (pr) { bd[p] = vv; bi[p] = ii; }
                pr = sh;
            }
            if (pr) { bd[0] = d; bi[0] = j; }
        }
    }

#pragma unroll
    for (int k = 0; k < 32; k++) {
        sd[(sub * 33 + k) * 64 + ql] = bd[k];
        si[(sub * 33 + k) * 64 + ql] = bi[k];
    }
    sd[(sub * 33 + 32) * 64 + ql] = 3.4e38f;
    si[(sub * 33 + 32) * 64 + ql] = 0x7fffffff;
    __syncthreads();

    if (tid < 64) {
        const int q = tid;
        const int qgl = blockIdx.x * 64 + q;
        const int base = (qgl >> 12) * NPTS;
        int c0 = 0, c1 = 0, c2 = 0, c3 = 0;
        float d0 = sd[(0*33)*64+q], d1 = sd[(1*33)*64+q],
              d2 = sd[(2*33)*64+q], d3 = sd[(3*33)*64+q];
        int   i0 = si[(0*33)*64+q], i1 = si[(1*33)*64+q],
              i2 = si[(2*33)*64+q], i3 = si[(3*33)*64+q];
        int* o = knn + (size_t)qgl * KNN_K;
#pragma unroll 1
        for (int r = 0; r < 32; r++) {
            float bdv = d0; int biv = i0; int sel = 0;
            if (d1 < bdv || (d1 == bdv && i1 < biv)) { bdv = d1; biv = i1; sel = 1; }
            if (d2 < bdv || (d2 == bdv && i2 < biv)) { bdv = d2; biv = i2; sel = 2; }
            if (d3 < bdv || (d3 == bdv && i3 < biv)) { bdv = d3; biv = i3; sel = 3; }
            if (!(r & 1)) o[r >> 1] = base + biv;
            if (sel == 0)      { c0++; d0 = sd[(0*33+c0)*64+q]; i0 = si[(0*33+c0)*64+q]; }
            else if (sel == 1) { c1++; d1 = sd[(1*33+c1)*64+q]; i1 = si[(1*33+c1)*64+q]; }
            else if (sel == 2) { c2++; d2 = sd[(2*33+c2)*64+q]; i2 = si[(2*33+c2)*64+q]; }
            else               { c3++; d3 = sd[(3*33+c3)*64+q]; i3 = si[(3*33+c3)*64+q]; }
        }
    }
}

// ---------------- fp16 GEMM config ----------------
#define KC 64
#define SH 72
#define STG_B 18432
#define NSTAGE 3
#define GEMM_SMEM (NSTAGE * 2 * STG_B)

template<int MODE, bool OUTH>
__global__ __launch_bounds__(256, 2) void gemm_h(
    int M, int N, int K,
    const __half* __restrict__ A, const __half* __restrict__ WT,
    const float* __restrict__ bias, const float* __restrict__ extra,
    void* __restrict__ Cout,
    const __half* __restrict__ pe, const __half* __restrict__ vf,
    __half* __restrict__ resh, const int* __restrict__ knn)
{
    extern __shared__ __align__(16) char smraw[];
    const uint32_t sbase = smem_u32(smraw);

    const int tid = threadIdx.x;
    const int bm = blockIdx.y * 128, bn = blockIdx.x * 128;
    const int lane = tid & 31, gid = lane >> 2, tig = lane & 3;
    const int w = tid >> 5, wm = w & 1, wn = w >> 1;
    const int lg = lane >> 3;

    const uint32_t aoff = ((uint32_t)(wm * 64 + (lg & 1) * 8 + (lane & 7)) * SH
                           + (lg >> 1) * 8) * 2;
    const uint32_t boff = ((uint32_t)(wn * 32 + (lg >> 1) * 8 + (lane & 7)) * SH
                           + (lg & 1) * 8) * 2;

    float acc[4][4][4];
#pragma unroll
    for (int i = 0; i < 4; i++)
#pragma unroll
        for (int j = 0; j < 4; j++)
#pragma unroll
            for (int r = 0; r < 4; r++) acc[i][j][r] = 0.0f;

    const int Cn = K / KC;
    const int cprow = tid >> 1;
    const int cpho  = (tid & 1) * 32;

    auto issue = [&](int c) {
        uint32_t st = sbase + (uint32_t)(c % NSTAGE) * (2 * STG_B);
        uint32_t bs = st + STG_B;
        const __half* Ag = A  + (size_t)(bm + cprow) * K + c * KC + cpho;
        const __half* Bg = WT + (size_t)(bn + cprow) * K + c * KC + cpho;
        uint32_t so = (uint32_t)(cprow * SH + cpho) * 2;
#pragma unroll
        for (int t = 0; t < 4; t++) {
            CP16(st + so + 16 * t, Ag + 8 * t);
            CP16(bs + so + 16 * t, Bg + 8 * t);
        }
        CP_COMMIT();
    };

    issue(0);
    issue(1);
    for (int c = 0; c < Cn; c++) {
        if (c == Cn - 1) cp_wait<0>(); else cp_wait<1>();
        __syncthreads();
        if (c + 2 < Cn) issue(c + 2);

        const uint32_t abase = sbase + (uint32_t)(c % NSTAGE) * (2 * STG_B) + aoff;
        const uint32_t bbase = sbase + (uint32_t)(c % NSTAGE) * (2 * STG_B) + STG_B + boff;

#pragma unroll
        for (int kk = 0; kk < 4; kk++) {
            uint32_t af[4][4], bf[4][2];
#pragma unroll
            for (int i = 0; i < 4; i++)
                LDSM_X4(af[i][0], af[i][1], af[i][2], af[i][3],
                        abase + i * (16 * SH * 2) + kk * 32);
#pragma unroll
            for (int jp = 0; jp < 2; jp++)
                LDSM_X4(bf[2*jp][0], bf[2*jp][1], bf[2*jp+1][0], bf[2*jp+1][1],
                        bbase + jp * (16 * SH * 2) + kk * 32);
#pragma unroll
            for (int i = 0; i < 4; i++)
#pragma unroll
                for (int j = 0; j < 4; j++)
                    mma_f16(acc[i][j], af[i], bf[j]);
        }
    }

    const int rowbase = bm + wm * 64;
    const int colbase = bn + wn * 32 + tig * 2;

    if constexpr (MODE == 0) {
#pragma unroll
        for (int i = 0; i < 4; i++) {
            int r0 = rowbase + i * 16 + gid;
#pragma unroll
            for (int j = 0; j < 4; j++) {
                int col = colbase + j * 8;
                float2 v0 = make_float2(acc[i][j][0], acc[i][j][1]);
                float2 v1 = make_float2(acc[i][j][2], acc[i][j][3]);
                if (bias) {
                    float2 bb = *reinterpret_cast<const float2*>(bias + col);
                    v0.x += bb.x; v0.y += bb.y; v1.x += bb.x; v1.y += bb.y;
                }
                if (extra) {
                    float2 e0 = *reinterpret_cast<const float2*>(extra + (size_t)r0 * N + col);
                    float2 e1 = *reinterpret_cast<const float2*>(extra + (size_t)(r0 + 8) * N + col);
                    v0.x += e0.x; v0.y += e0.y; v1.x += e1.x; v1.y += e1.y;
                }
                if (OUTH) {
                    __half* Ch = (__half*)Cout;
                    *reinterpret_cast<__half2*>(Ch + (size_t)r0 * N + col) = __floats2half2_rn(v0.x, v0.y);
                    *reinterpret_cast<__half2*>(Ch + (size_t)(r0 + 8) * N + col) = __floats2half2_rn(v1.x, v1.y);
                } else {
                    float* Cf = (float*)Cout;
                    *reinterpret_cast<float2*>(Cf + (size_t)r0 * N + col) = v0;
                    *reinterpret_cast<float2*>(Cf + (size_t)(r0 + 8) * N + col) = v1;
                }
            }
        }
    } else {  // MODE 2
        float* Cf = (float*)Cout;
#pragma unroll
        for (int i = 0; i < 4; i++) {
            int r0 = rowbase + i * 16 + gid;
            int r1 = r0 + 8;
            int n = r0 >> 4;
            int j1 = knn[r0], j2 = knn[r1];
#pragma unroll
            for (int j = 0; j < 4; j++) {
                int col = colbase + j * 8;
                float2 bb = *reinterpret_cast<const float2*>(bias + col);
                float a0 = acc[i][j][0] + bb.x;
                float a1 = acc[i][j][1] + bb.y;
                float a2 = acc[i][j][2] + bb.x;
                float a3 = acc[i][j][3] + bb.y;
                float m0 = rmax8(fmaxf(a0, a2));
                float m1 = rmax8(fmaxf(a1, a3));
                float e0 = __expf((a0 - m0) * INV_SCALE);
                float e1 = __expf((a1 - m1) * INV_SCALE);
                float e2 = __expf((a2 - m0) * INV_SCALE);
                float e3 = __expf((a3 - m1) * INV_SCALE);
                float inv0 = 1.0f / rsum8(e0 + e2);
                float inv1 = 1.0f / rsum8(e1 + e3);
                float at0 = e0 * inv0, at1 = e1 * inv1;
                float at2 = e2 * inv0, at3 = e3 * inv1;
                *reinterpret_cast<float2*>(Cf + (size_t)r0 * DM + col) = make_float2(at0, at1);
                *reinterpret_cast<float2*>(Cf + (size_t)r1 * DM + col) = make_float2(at2, at3);
                float2 p0 = __half22float2(*reinterpret_cast<const __half2*>(pe + (size_t)r0 * DM + col));
                float2 p1 = __half22float2(*reinterpret_cast<const __half2*>(pe + (size_t)r1 * DM + col));
                float2 w1 = __half22float2(*reinterpret_cast<const __half2*>(vf + (size_t)j1 * KVS + col));
                float2 w2 = __half22float2(*reinterpret_cast<const __half2*>(vf + (size_t)j2 * KVS + col));
                float px = at0 * (w1.x + p0.x) + at2 * (w2.x + p1.x);
                float py = at1 * (w1.y + p0.y) + at3 * (w2.y + p1.y);
                px = rsum8(px);
                py = rsum8(py);
                if (gid == 0)
                    *reinterpret_cast<__half2*>(resh + (size_t)n * DM + col) =
                        __floats2half2_rn(px, py);
            }
        }
    }
}

// ---------------- GEN dual GEMM v2: A-resident, 16 B-tiles per CTA ----------------
// smem: A chunks 0-3 at c*STG_B; B bufs at (4+b)*STG_B; rel 3x128 f; knn 128 i
#define GEN_SMEM (6 * STG_B + 2048)    // 112640 B -> 2 CTAs/SM

__global__ __launch_bounds__(256, 2) void gen_dual_kernel(
    const __half* __restrict__ WT,
    const float* __restrict__ xyz1, const float* __restrict__ xyz2,
    const float* __restrict__ Wd1, const float* __restrict__ bd1,
    const float* __restrict__ bias,
    __half* __restrict__ pe_out, __half* __restrict__ t2_out,
    const float* __restrict__ cc,
    const float* __restrict__ qg, const __half* __restrict__ kg,
    const int* __restrict__ knn)
{
    extern __shared__ __align__(16) char smraw[];
    const uint32_t sbase = smem_u32(smraw);

    float* smrel = (float*)(smraw + 6 * STG_B);   // [3][128]
    int*   smknn = (int*)(smrel + 384);           // [128]

    const int tid = threadIdx.x;
    const int bm = blockIdx.x * 128;
    const int lane = tid & 31, gid = lane >> 2, tig = lane & 3;
    const int w = tid >> 5, wm = w & 1, wn = w >> 1;
    const int lg = lane >> 3;

    const uint32_t aoff = ((uint32_t)(wm * 64 + (lg & 1) * 8 + (lane & 7)) * SH
                           + (lg >> 1) * 8) * 2;
    const uint32_t boff = ((uint32_t)(wn * 32 + (lg >> 1) * 8 + (lane & 7)) * SH
                           + (lg & 1) * 8) * 2;

    const int cprow = tid >> 1;
    const int cpho  = (tid & 1) * 32;

    // B tile m: nt = m>>2 (N-tile), c = m&3 (K-chunk); buffer m&1
    auto issueB = [&](int m) {
        uint32_t bs = sbase + (uint32_t)(4 + (m & 1)) * STG_B;
        const __half* Bg = WT + (size_t)((m >> 2) * 128 + cprow) * DM + (m & 3) * KC + cpho;
        uint32_t so = (uint32_t)(cprow * SH + cpho) * 2;
#pragma unroll
        for (int t = 0; t < 4; t++) CP16(bs + so + 16 * t, Bg + 8 * t);
        CP_COMMIT();
    };

    issueB(0);                                      // overlap with prologue + A-gen

    // prologue: rel + knn
    if (tid < 128) {
        int j = knn[bm + tid];
        smknn[tid] = j;
        int q = (bm + tid) >> 4;
        smrel[tid]       = xyz1[(size_t)q * 3 + 0] - xyz2[(size_t)j * 3 + 0];
        smrel[128 + tid] = xyz1[(size_t)q * 3 + 1] - xyz2[(size_t)j * 3 + 1];
        smrel[256 + tid] = xyz1[(size_t)q * 3 + 2] - xyz2[(size_t)j * 3 + 2];
    }
    __syncthreads();                                // rel visible for A-gen

    // generate all 4 A chunks (each thread: row grow, 32 cols at gho, per chunk)
    {
        const int grow = tid >> 1;
        const int gho  = (tid & 1) * 32;
        const float r0v = smrel[grow];
        const float r1v = smrel[128 + grow];
        const float r2v = smrel[256 + grow];
#pragma unroll 1
        for (int c = 0; c < 4; c++) {
            __half2 hb[16];
            const int cb = c * KC + gho;
#pragma unroll
            for (int u = 0; u < 16; u++) {
                int ci = cb + u * 2;
                float v0 = fmaf(r0v, __ldg(Wd1 + ci),
                           fmaf(r1v, __ldg(Wd1 + 256 + ci),
                           fmaf(r2v, __ldg(Wd1 + 512 + ci), __ldg(bd1 + ci))));
                float v1 = fmaf(r0v, __ldg(Wd1 + ci + 1),
                           fmaf(r1v, __ldg(Wd1 + 256 + ci + 1),
                           fmaf(r2v, __ldg(Wd1 + 512 + ci + 1), __ldg(bd1 + ci + 1))));
                hb[u] = __floats2half2_rn(fmaxf(v0, 0.f), fmaxf(v1, 0.f));
            }
            __half* dst = (__half*)(smraw + c * STG_B) + grow * SH + gho;
#pragma unroll
            for (int t = 0; t < 4; t++)
                *reinterpret_cast<uint4*>(dst + 8 * t) = *reinterpret_cast<uint4*>(&hb[4 * t]);
        }
    }

    float acc[4][4][4];
#pragma unroll
    for (int i = 0; i < 4; i++)
#pragma unroll
        for (int j = 0; j < 4; j++)
#pragma unroll
            for (int r = 0; r < 4; r++) acc[i][j][r] = 0.0f;

    const int rowbase = bm + wm * 64;

#pragma unroll 1
    for (int m = 0; m < 16; m++) {
        cp_wait<0>();
        __syncthreads();            // B(m) ready; all warps done with buffer (m+1)&1
        if (m < 15) issueB(m + 1);  // overlaps with compute below

        const uint32_t abase = sbase + (uint32_t)(m & 3) * STG_B + aoff;
        const uint32_t bbase = sbase + (uint32_t)(4 + (m & 1)) * STG_B + boff;

#pragma unroll
        for (int kk = 0; kk < 4; kk++) {
            uint32_t af[4][4], bf[4][2];
#pragma unroll
            for (int i = 0; i < 4; i++)
                LDSM_X4(af[i][0], af[i][1], af[i][2], af[i][3],
                        abase + i * (16 * SH * 2) + kk * 32);
#pragma unroll
            for (int jp = 0; jp < 2; jp++)
                LDSM_X4(bf[2*jp][0], bf[2*jp][1], bf[2*jp+1][0], bf[2*jp+1][1],
                        bbase + jp * (16 * SH * 2) + kk * 32);
#pragma unroll
            for (int i = 0; i < 4; i++)
#pragma unroll
                for (int j = 0; j < 4; j++)
                    mma_f16(acc[i][j], af[i], bf[j]);
        }

        if ((m & 3) == 3) {
            // epilogue for N-tile nt = m>>2
            const int nt = m >> 2;
            const bool isPE = (nt < 2);
            const int colbase = nt * 128 + wn * 32 + tig * 2;
#pragma unroll
            for (int i = 0; i < 4; i++) {
                int r0 = rowbase + i * 16 + gid;
                int r1 = r0 + 8;
                int n = r0 >> 4;
                int j1 = 0, j2 = 0;
                if (!isPE) { j1 = smknn[r0 - bm]; j2 = smknn[r1 - bm]; }
#pragma unroll
                for (int j = 0; j < 4; j++) {
                    int col = colbase + j * 8;
                    if (isPE) {
                        float2 bb = *reinterpret_cast<const float2*>(bias + col);
                        *reinterpret_cast<__half2*>(pe_out + (size_t)r0 * DM + col) =
                            __floats2half2_rn(acc[i][j][0] + bb.x, acc[i][j][1] + bb.y);
                        *reinterpret_cast<__half2*>(pe_out + (size_t)r1 * DM + col) =
                            __floats2half2_rn(acc[i][j][2] + bb.x, acc[i][j][3] + bb.y);
                    } else {
                        int c2 = col - 256;
                        float2 ccv = *reinterpret_cast<const float2*>(cc + c2);
                        float2 qv  = *reinterpret_cast<const float2*>(qg + (size_t)n * DM + c2);
                        float2 k1  = __half22float2(*reinterpret_cast<const __half2*>(kg + (size_t)j1 * KVS + c2));
                        float2 k2  = __half22float2(*reinterpret_cast<const __half2*>(kg + (size_t)j2 * KVS + c2));
                        *reinterpret_cast<__half2*>(t2_out + (size_t)r0 * DM + c2) =
                            __floats2half2_rn(fmaxf(acc[i][j][0] + ccv.x + qv.x - k1.x, 0.f),
                                              fmaxf(acc[i][j][1] + ccv.y + qv.y - k1.y, 0.f));
                        *reinterpret_cast<__half2*>(t2_out + (size_t)r1 * DM + c2) =
                            __floats2half2_rn(fmaxf(acc[i][j][2] + ccv.x + qv.x - k2.x, 0.f),
                                              fmaxf(acc[i][j][3] + ccv.y + qv.y - k2.y, 0.f));
                    }
                }
            }
#pragma unroll
            for (int i = 0; i < 4; i++)
#pragma unroll
                for (int j = 0; j < 4; j++)
#pragma unroll
                    for (int r = 0; r < 4; r++) acc[i][j][r] = 0.0f;
        }
    }
}

// ---------------- host launch ----------------
template<int MODE, bool OUTH>
static void launch_h(int M, int N, int K,
                     const __half* A, const __half* WT,
                     const float* bias, const float* extra, void* Cout,
                     const __half* pe = nullptr, const __half* vf = nullptr,
                     __half* resh = nullptr, const int* knn = nullptr)
{
    cudaFuncSetAttribute(gemm_h<MODE, OUTH>,
                         cudaFuncAttributeMaxDynamicSharedMemorySize, GEMM_SMEM);
    gemm_h<MODE, OUTH><<<dim3(N / 128, M / 128), 256, GEMM_SMEM>>>(
        M, N, K, A, WT, bias, extra, Cout, pe, vf, resh, knn);
}

extern "C" void kernel_launch(void* const* d_in, const int* in_sizes, int n_in,
                              void* d_out, int out_size)
{
    const float* xyz1      = (const float*)d_in[0];
    const float* features1 = (const float*)d_in[1];
    const float* xyz2      = (const float*)d_in[2];
    const float* features2 = (const float*)d_in[3];
    const float* W_fc1     = (const float*)d_in[4];
    const float* b_fc1     = (const float*)d_in[5];
    const float* W_fc2     = (const float*)d_in[6];
    const float* b_fc2     = (const float*)d_in[7];
    const float* Wd1       = (const float*)d_in[8];
    const float* bd1       = (const float*)d_in[9];
    const float* Wd2       = (const float*)d_in[10];
    const float* bd2       = (const float*)d_in[11];
    const float* Wg1       = (const float*)d_in[12];
    const float* bg1       = (const float*)d_in[13];
    const float* Wg2       = (const float*)d_in[14];
    const float* bg2       = (const float*)d_in[15];
    const float* Wq        = (const float*)d_in[16];
    const float* Wk        = (const float*)d_in[17];
    const float* Wv        = (const float*)d_in[18];

    float* out_res  = (float*)d_out;
    float* out_attn = (float*)d_out + (size_t)BN * DP;

    int*    p_knn;  cudaGetSymbolAddress((void**)&p_knn,  g_knn);
    float4* p_sp4;  cudaGetSymbolAddress((void**)&p_sp4,  g_sp4);
    __half* p_f1h;  cudaGetSymbolAddress((void**)&p_f1h,  g_f1h);
    __half* p_f2h;  cudaGetSymbolAddress((void**)&p_f2h,  g_f2h);
    __half* p_x1h;  cudaGetSymbolAddress((void**)&p_x1h,  g_x1h);
    __half* p_x2h;  cudaGetSymbolAddress((void**)&p_x2h,  g_x2h);
    float*  p_qg;   cudaGetSymbolAddress((void**)&p_qg,   g_qg);
    __half* p_kgvf; cudaGetSymbolAddress((void**)&p_kgvf, g_kgvfh);
    __half* p_resh; cudaGetSymbolAddress((void**)&p_resh, g_resh);
    __half* p_t2h;  cudaGetSymbolAddress((void**)&p_t2h,  g_t2h);
    __half* p_peh;  cudaGetSymbolAddress((void**)&p_peh,  g_peh);
    __half* w_fc1;  cudaGetSymbolAddress((void**)&w_fc1,  g_wfc1h);
    __half* w_fc2;  cudaGetSymbolAddress((void**)&w_fc2,  g_wfc2h);
    __half* w_dual; cudaGetSymbolAddress((void**)&w_dual, g_wdualh);
    __half* w_g2;   cudaGetSymbolAddress((void**)&w_g2,   g_wg2h);
    __half* w_qg;   cudaGetSymbolAddress((void**)&w_qg,   g_wqgh);
    __half* w_kv;   cudaGetSymbolAddress((void**)&w_kv,   g_wkvh);
    float*  p_cc;   cudaGetSymbolAddress((void**)&p_cc,   g_cc);

    cudaFuncSetAttribute(gen_dual_kernel,
                         cudaFuncAttributeMaxDynamicSharedMemorySize, GEN_SMEM);
    cudaFuncSetAttribute(knn_kernel,
                         cudaFuncAttributeMaxDynamicSharedMemorySize, KNN_SMEM);

    static cudaStream_t sB = nullptr;
    static cudaEvent_t evF = nullptr, evJ = nullptr;
    if (sB == nullptr) {
        cudaStreamCreateWithFlags(&sB, cudaStreamNonBlocking);
        cudaEventCreateWithFlags(&evF, cudaEventDisableTiming);
        cudaEventCreateWithFlags(&evJ, cudaEventDisableTiming);
    }

    dim3 tb(32, 8);

    // ---- fork: stream B runs the ALU-bound KNN branch ----
    cudaEventRecord(evF, 0);
    cudaStreamWaitEvent(sB, evF, 0);
    prep_pts<<<BN / 256, 256, 0, sB>>>(xyz2, p_sp4);
    knn_kernel<<<BN / 64, 256, KNN_SMEM, sB>>>(xyz1, p_sp4, p_knn);
    cudaEventRecord(evJ, sB);

    // ---- stream 0: tensor-bound prep + projection chain ----
    transpose_kernel<<<dim3(DM/32, DP/32), tb>>>(W_fc1, w_fc1, DP, DM);
    f2h_kernel<<<(BN * DP) / 1024, 256>>>(features1, p_f1h);
    f2h_kernel<<<(BN * DP) / 1024, 256>>>(features2, p_f2h);
    transpose_kernel<<<dim3(DM/32, DM/32), tb>>>(Wd2,  w_dual, DM, DM);
    transpose_kernel<<<dim3(DM/32, DM/32), tb>>>(Wg2,  w_g2, DM, DM);
    transpose_kernel<<<dim3(DM/32, DM/32), tb>>>(Wv,   w_kv + DM * DM, DM, DM);
    transpose_kernel<<<dim3(DP/32, DM/32), tb>>>(W_fc2, w_fc2, DM, DP);
    combine_kernel<<<DM, DM>>>(Wq,  Wg1, w_qg);
    combine_kernel<<<DM, DM>>>(Wk,  Wg1, w_kv);
    combine_kernel<<<DM, DM>>>(Wd2, Wg1, w_dual + DM * DM);
    cc_kernel<<<1, DM>>>(bd2, Wg1, bg1, p_cc);

    launch_h<0, true >(BN, DM, DP, p_f1h, w_fc1, b_fc1, nullptr, p_x1h);
    launch_h<0, true >(BN, DM, DP, p_f2h, w_fc1, b_fc1, nullptr, p_x2h);
    launch_h<0, false>(BN, DM, DM, p_x1h, w_qg, nullptr, nullptr, p_qg);
    launch_h<0, true >(BN, KVS, DM, p_x2h, w_kv, nullptr, nullptr, p_kgvf);

    // ---- join: gen_dual needs knn + qg + kgvf ----
    cudaStreamWaitEvent(0, evJ, 0);

    gen_dual_kernel<<<BNK / 128, 256, GEN_SMEM>>>(
        w_dual, xyz1, xyz2, Wd1, bd1, bd2, p_peh, p_t2h, p_cc, p_qg, p_kgvf, p_knn);

    launch_h<2, false>(BNK, DM, DM, p_t2h, w_g2, bg2, nullptr, out_attn,
                       p_peh, p_kgvf + 256, p_resh, p_knn);

    launch_h<0, false>(BN, DP, DM, p_resh, w_fc2, b_fc2, features1, out_res);
}

// round 17
// speedup vs baseline: 1.3135x; 1.1855x over previous
#include <cuda_runtime.h>
#include <cuda_fp16.h>
#include <cstdint>
#include <math.h>

// ---------------- problem constants ----------------
#define BATCH 4
#define NPTS  4096
#define BN    (BATCH*NPTS)          // 16384
#define DP    128
#define DM    256
#define KNN_K 16
#define BNK   (BN*KNN_K)            // 262144
#define INV_SCALE 0.0625f           // 1/sqrt(256)
#define KVS   512                   // row stride of merged kg|vf buffer

// ---------------- device scratch ----------------
__device__ int    g_knn[BNK];                // GLOBAL point index
__device__ float4 g_sp4[BN];                 // xyz2 + norm
__device__ __half g_f1h[BN * DP];
__device__ __half g_f2h[BN * DP];
__device__ __half g_x1h[BN * DM];
__device__ __half g_x2h[BN * DM];
__device__ float  g_qg [BN * DM];
__device__ __half g_kgvfh[BN * KVS];         // fp16: cols 0-255 kg, 256-511 vf
__device__ __half g_resh[BN * DM];
__device__ __half g_t2h[(size_t)BNK * DM];
__device__ __half g_peh[(size_t)BNK * DM];   // pos_enc fp16
// fp16 weights, [N rows][K cols] K-major
__device__ __half g_wfc1h[DM * DP];
__device__ __half g_wfc2h[DP * DM];
__device__ __half g_wdualh[2 * DM * DM];
__device__ __half g_wg2h [DM * DM];
__device__ __half g_wqgh [DM * DM];
__device__ __half g_wkvh [2 * DM * DM];
__device__ float  g_cc [DM];

// ---------------- PTX helpers ----------------
__device__ __forceinline__ uint32_t smem_u32(const void* p) {
    uint32_t a;
    asm("{ .reg .u64 t; cvta.to.shared.u64 t, %1; cvt.u32.u64 %0, t; }" : "=r"(a) : "l"(p));
    return a;
}
#define CP16(dst, src) \
    asm volatile("cp.async.cg.shared.global [%0], [%1], 16;" :: "r"(dst), "l"(src))
#define CP_COMMIT() asm volatile("cp.async.commit_group;" ::: "memory")
template <int N> __device__ __forceinline__ void cp_wait() {
    asm volatile("cp.async.wait_group %0;" :: "n"(N) : "memory");
}
#define LDSM_X4(r0, r1, r2, r3, addr) \
    asm volatile("ldmatrix.sync.aligned.m8n8.x4.shared.b16 {%0,%1,%2,%3}, [%4];" \
        : "=r"(r0), "=r"(r1), "=r"(r2), "=r"(r3) : "r"(addr))

__device__ __forceinline__ void mma_f16(float* d, const uint32_t* a, const uint32_t* b) {
    asm volatile(
        "mma.sync.aligned.m16n8k16.row.col.f32.f16.f16.f32 "
        "{%0,%1,%2,%3},{%4,%5,%6,%7},{%8,%9},{%0,%1,%2,%3};"
        : "+f"(d[0]), "+f"(d[1]), "+f"(d[2]), "+f"(d[3])
        : "r"(a[0]), "r"(a[1]), "r"(a[2]), "r"(a[3]), "r"(b[0]), "r"(b[1]));
}

__device__ __forceinline__ float rmax8(float v) {
    v = fmaxf(v, __shfl_xor_sync(0xffffffffu, v, 4));
    v = fmaxf(v, __shfl_xor_sync(0xffffffffu, v, 8));
    v = fmaxf(v, __shfl_xor_sync(0xffffffffu, v, 16));
    return v;
}
__device__ __forceinline__ float rsum8(float v) {
    v += __shfl_xor_sync(0xffffffffu, v, 4);
    v += __shfl_xor_sync(0xffffffffu, v, 8);
    v += __shfl_xor_sync(0xffffffffu, v, 16);
    return v;
}

// ---------------- prep kernels ----------------
__global__ void prep_pts(const float* __restrict__ xyz2, float4* __restrict__ sp4)
{
    int i = blockIdx.x * 256 + threadIdx.x;
    float x = xyz2[3*i], y = xyz2[3*i+1], z = xyz2[3*i+2];
    sp4[i] = make_float4(x, y, z, x*x + y*y + z*z);
}

__global__ void f2h_kernel(const float* __restrict__ in, __half* __restrict__ out)
{
    int i = (blockIdx.x * 256 + threadIdx.x) * 4;
    float4 v = *reinterpret_cast<const float4*>(in + i);
    __half2* o = reinterpret_cast<__half2*>(out + i);
    o[0] = __floats2half2_rn(v.x, v.y);
    o[1] = __floats2half2_rn(v.z, v.w);
}

__global__ void transpose_kernel(const float* __restrict__ W, __half* __restrict__ WT,
                                 int K, int N)
{
    __shared__ float t[32][33];
    int bx = blockIdx.x * 32, by = blockIdx.y * 32;
    int tx = threadIdx.x, ty = threadIdx.y;
#pragma unroll
    for (int i = 0; i < 32; i += 8)
        t[ty + i][tx] = W[(size_t)(by + ty + i) * N + bx + tx];
    __syncthreads();
#pragma unroll
    for (int i = 0; i < 32; i += 8)
        WT[(size_t)(bx + ty + i) * K + by + tx] = __float2half(t[tx][ty + i]);
}

__global__ void combine_kernel(const float* __restrict__ W1, const float* __restrict__ W2,
                               __half* __restrict__ outT)
{
    __shared__ float colv[DM];
    int n = blockIdx.x, k = threadIdx.x;
    colv[k] = W2[k * DM + n];
    __syncthreads();
    const float* w = W1 + k * DM;
    float s = 0.0f;
#pragma unroll 8
    for (int m = 0; m < DM; m++) s = fmaf(w[m], colv[m], s);
    outT[n * DM + k] = __float2half(s);
}

__global__ void cc_kernel(const float* __restrict__ bd2, const float* __restrict__ Wg1,
                          const float* __restrict__ bg1, float* __restrict__ cc)
{
    int n = threadIdx.x;
    float s = bg1[n];
#pragma unroll 8
    for (int m = 0; m < DM; m++) s = fmaf(bd2[m], Wg1[m * DM + n], s);
    cc[n] = s;
}

// ---------------- KNN: warp-per-query, lane-distributed sorted list ----------------
// list ascending across lanes (lane0 = nearest). O(1) ballot/shfl insertion.
__global__ __launch_bounds__(256) void knn_kernel(
    const float* __restrict__ xyz1, const float4* __restrict__ sp4g,
    int* __restrict__ knn)
{
    const int tid  = threadIdx.x;
    const int lane = tid & 31;
    const int wq   = blockIdx.x * 8 + (tid >> 5);   // global query (one warp each)
    const int b    = wq >> 12;

    const float qx = xyz1[3*wq], qy = xyz1[3*wq+1], qz = xyz1[3*wq+2];
    const float qn = qx*qx + qy*qy + qz*qz;

    float listd = 3.4e38f;
    int   listi = 0x7fffffff;
    float curmax = 3.4e38f;

    const float4* sp = sp4g + b * NPTS;
#pragma unroll 1
    for (int t0 = 0; t0 < NPTS; t0 += 32) {
        float4 c = __ldg(sp + t0 + lane);
        float d = qn + c.w - 2.0f * (qx*c.x + qy*c.y + qz*c.z);
        unsigned q = __ballot_sync(0xffffffffu, d < curmax);
        while (q) {
            int src = __ffs(q) - 1;          // lowest index first -> stable tie order
            q &= q - 1;
            float dd = __shfl_sync(0xffffffffu, d, src);
            if (dd < curmax) {               // warp-uniform (dd broadcast)
                int ii = t0 + src;
                unsigned le = __ballot_sync(0xffffffffu, listd <= dd);
                int pos = __popc(le);        // insert after equals (stable)
                float ud = __shfl_up_sync(0xffffffffu, listd, 1);
                int   ui = __shfl_up_sync(0xffffffffu, listi, 1);
                if (lane > pos)       { listd = ud; listi = ui; }
                else if (lane == pos) { listd = dd; listi = ii; }
                curmax = __shfl_sync(0xffffffffu, listd, 31);
            }
        }
    }
    // even ranks 0,2,...,30 -> knn[wq][0..15]
    if (!(lane & 1))
        knn[(size_t)wq * KNN_K + (lane >> 1)] = b * NPTS + listi;
}

// ---------------- fp16 GEMM config ----------------
#define KC 64
#define SH 72
#define STG_B 18432
#define NSTAGE 3
#define GEMM_SMEM (NSTAGE * 2 * STG_B)

template<int MODE, bool OUTH>
__global__ __launch_bounds__(256, 2) void gemm_h(
    int M, int N, int K,
    const __half* __restrict__ A, const __half* __restrict__ WT,
    const float* __restrict__ bias, const float* __restrict__ extra,
    void* __restrict__ Cout,
    const __half* __restrict__ pe, const __half* __restrict__ vf,
    __half* __restrict__ resh, const int* __restrict__ knn)
{
    extern __shared__ __align__(16) char smraw[];
    const uint32_t sbase = smem_u32(smraw);

    const int tid = threadIdx.x;
    const int bm = blockIdx.y * 128, bn = blockIdx.x * 128;
    const int lane = tid & 31, gid = lane >> 2, tig = lane & 3;
    const int w = tid >> 5, wm = w & 1, wn = w >> 1;
    const int lg = lane >> 3;

    const uint32_t aoff = ((uint32_t)(wm * 64 + (lg & 1) * 8 + (lane & 7)) * SH
                           + (lg >> 1) * 8) * 2;
    const uint32_t boff = ((uint32_t)(wn * 32 + (lg >> 1) * 8 + (lane & 7)) * SH
                           + (lg & 1) * 8) * 2;

    float acc[4][4][4];
#pragma unroll
    for (int i = 0; i < 4; i++)
#pragma unroll
        for (int j = 0; j < 4; j++)
#pragma unroll
            for (int r = 0; r < 4; r++) acc[i][j][r] = 0.0f;

    const int Cn = K / KC;
    const int cprow = tid >> 1;
    const int cpho  = (tid & 1) * 32;

    auto issue = [&](int c) {
        uint32_t st = sbase + (uint32_t)(c % NSTAGE) * (2 * STG_B);
        uint32_t bs = st + STG_B;
        const __half* Ag = A  + (size_t)(bm + cprow) * K + c * KC + cpho;
        const __half* Bg = WT + (size_t)(bn + cprow) * K + c * KC + cpho;
        uint32_t so = (uint32_t)(cprow * SH + cpho) * 2;
#pragma unroll
        for (int t = 0; t < 4; t++) {
            CP16(st + so + 16 * t, Ag + 8 * t);
            CP16(bs + so + 16 * t, Bg + 8 * t);
        }
        CP_COMMIT();
    };

    issue(0);
    issue(1);
    for (int c = 0; c < Cn; c++) {
        if (c == Cn - 1) cp_wait<0>(); else cp_wait<1>();
        __syncthreads();
        if (c + 2 < Cn) issue(c + 2);

        const uint32_t abase = sbase + (uint32_t)(c % NSTAGE) * (2 * STG_B) + aoff;
        const uint32_t bbase = sbase + (uint32_t)(c % NSTAGE) * (2 * STG_B) + STG_B + boff;

#pragma unroll
        for (int kk = 0; kk < 4; kk++) {
            uint32_t af[4][4], bf[4][2];
#pragma unroll
            for (int i = 0; i < 4; i++)
                LDSM_X4(af[i][0], af[i][1], af[i][2], af[i][3],
                        abase + i * (16 * SH * 2) + kk * 32);
#pragma unroll
            for (int jp = 0; jp < 2; jp++)
                LDSM_X4(bf[2*jp][0], bf[2*jp][1], bf[2*jp+1][0], bf[2*jp+1][1],
                        bbase + jp * (16 * SH * 2) + kk * 32);
#pragma unroll
            for (int i = 0; i < 4; i++)
#pragma unroll
                for (int j = 0; j < 4; j++)
                    mma_f16(acc[i][j], af[i], bf[j]);
        }
    }

    const int rowbase = bm + wm * 64;
    const int colbase = bn + wn * 32 + tig * 2;

    if constexpr (MODE == 0) {
#pragma unroll
        for (int i = 0; i < 4; i++) {
            int r0 = rowbase + i * 16 + gid;
#pragma unroll
            for (int j = 0; j < 4; j++) {
                int col = colbase + j * 8;
                float2 v0 = make_float2(acc[i][j][0], acc[i][j][1]);
                float2 v1 = make_float2(acc[i][j][2], acc[i][j][3]);
                if (bias) {
                    float2 bb = *reinterpret_cast<const float2*>(bias + col);
                    v0.x += bb.x; v0.y += bb.y; v1.x += bb.x; v1.y += bb.y;
                }
                if (extra) {
                    float2 e0 = *reinterpret_cast<const float2*>(extra + (size_t)r0 * N + col);
                    float2 e1 = *reinterpret_cast<const float2*>(extra + (size_t)(r0 + 8) * N + col);
                    v0.x += e0.x; v0.y += e0.y; v1.x += e1.x; v1.y += e1.y;
                }
                if (OUTH) {
                    __half* Ch = (__half*)Cout;
                    *reinterpret_cast<__half2*>(Ch + (size_t)r0 * N + col) = __floats2half2_rn(v0.x, v0.y);
                    *reinterpret_cast<__half2*>(Ch + (size_t)(r0 + 8) * N + col) = __floats2half2_rn(v1.x, v1.y);
                } else {
                    float* Cf = (float*)Cout;
                    *reinterpret_cast<float2*>(Cf + (size_t)r0 * N + col) = v0;
                    *reinterpret_cast<float2*>(Cf + (size_t)(r0 + 8) * N + col) = v1;
                }
            }
        }
    } else {  // MODE 2
        float* Cf = (float*)Cout;
#pragma unroll
        for (int i = 0; i < 4; i++) {
            int r0 = rowbase + i * 16 + gid;
            int r1 = r0 + 8;
            int n = r0 >> 4;
            int j1 = knn[r0], j2 = knn[r1];
#pragma unroll
            for (int j = 0; j < 4; j++) {
                int col = colbase + j * 8;
                float2 bb = *reinterpret_cast<const float2*>(bias + col);
                float a0 = acc[i][j][0] + bb.x;
                float a1 = acc[i][j][1] + bb.y;
                float a2 = acc[i][j][2] + bb.x;
                float a3 = acc[i][j][3] + bb.y;
                float m0 = rmax8(fmaxf(a0, a2));
                float m1 = rmax8(fmaxf(a1, a3));
                float e0 = __expf((a0 - m0) * INV_SCALE);
                float e1 = __expf((a1 - m1) * INV_SCALE);
                float e2 = __expf((a2 - m0) * INV_SCALE);
                float e3 = __expf((a3 - m1) * INV_SCALE);
                float inv0 = 1.0f / rsum8(e0 + e2);
                float inv1 = 1.0f / rsum8(e1 + e3);
                float at0 = e0 * inv0, at1 = e1 * inv1;
                float at2 = e2 * inv0, at3 = e3 * inv1;
                *reinterpret_cast<float2*>(Cf + (size_t)r0 * DM + col) = make_float2(at0, at1);
                *reinterpret_cast<float2*>(Cf + (size_t)r1 * DM + col) = make_float2(at2, at3);
                float2 p0 = __half22float2(*reinterpret_cast<const __half2*>(pe + (size_t)r0 * DM + col));
                float2 p1 = __half22float2(*reinterpret_cast<const __half2*>(pe + (size_t)r1 * DM + col));
                float2 w1 = __half22float2(*reinterpret_cast<const __half2*>(vf + (size_t)j1 * KVS + col));
                float2 w2 = __half22float2(*reinterpret_cast<const __half2*>(vf + (size_t)j2 * KVS + col));
                float px = at0 * (w1.x + p0.x) + at2 * (w2.x + p1.x);
                float py = at1 * (w1.y + p0.y) + at3 * (w2.y + p1.y);
                px = rsum8(px);
                py = rsum8(py);
                if (gid == 0)
                    *reinterpret_cast<__half2*>(resh + (size_t)n * DM + col) =
                        __floats2half2_rn(px, py);
            }
        }
    }
}

// ---------------- GEN dual GEMM: A-resident, 16 B-tiles per CTA ----------------
#define GEN_SMEM (6 * STG_B + 2048)    // 112640 B -> 2 CTAs/SM

__global__ __launch_bounds__(256, 2) void gen_dual_kernel(
    const __half* __restrict__ WT,
    const float* __restrict__ xyz1, const float* __restrict__ xyz2,
    const float* __restrict__ Wd1, const float* __restrict__ bd1,
    const float* __restrict__ bias,
    __half* __restrict__ pe_out, __half* __restrict__ t2_out,
    const float* __restrict__ cc,
    const float* __restrict__ qg, const __half* __restrict__ kg,
    const int* __restrict__ knn)
{
    extern __shared__ __align__(16) char smraw[];
    const uint32_t sbase = smem_u32(smraw);

    float* smrel = (float*)(smraw + 6 * STG_B);   // [3][128]
    int*   smknn = (int*)(smrel + 384);           // [128]

    const int tid = threadIdx.x;
    const int bm = blockIdx.x * 128;
    const int lane = tid & 31, gid = lane >> 2, tig = lane & 3;
    const int w = tid >> 5, wm = w & 1, wn = w >> 1;
    const int lg = lane >> 3;

    const uint32_t aoff = ((uint32_t)(wm * 64 + (lg & 1) * 8 + (lane & 7)) * SH
                           + (lg >> 1) * 8) * 2;
    const uint32_t boff = ((uint32_t)(wn * 32 + (lg >> 1) * 8 + (lane & 7)) * SH
                           + (lg & 1) * 8) * 2;

    const int cprow = tid >> 1;
    const int cpho  = (tid & 1) * 32;

    auto issueB = [&](int m) {
        uint32_t bs = sbase + (uint32_t)(4 + (m & 1)) * STG_B;
        const __half* Bg = WT + (size_t)((m >> 2) * 128 + cprow) * DM + (m & 3) * KC + cpho;
        uint32_t so = (uint32_t)(cprow * SH + cpho) * 2;
#pragma unroll
        for (int t = 0; t < 4; t++) CP16(bs + so + 16 * t, Bg + 8 * t);
        CP_COMMIT();
    };

    issueB(0);

    if (tid < 128) {
        int j = knn[bm + tid];
        smknn[tid] = j;
        int q = (bm + tid) >> 4;
        smrel[tid]       = xyz1[(size_t)q * 3 + 0] - xyz2[(size_t)j * 3 + 0];
        smrel[128 + tid] = xyz1[(size_t)q * 3 + 1] - xyz2[(size_t)j * 3 + 1];
        smrel[256 + tid] = xyz1[(size_t)q * 3 + 2] - xyz2[(size_t)j * 3 + 2];
    }
    __syncthreads();

    {
        const int grow = tid >> 1;
        const int gho  = (tid & 1) * 32;
        const float r0v = smrel[grow];
        const float r1v = smrel[128 + grow];
        const float r2v = smrel[256 + grow];
#pragma unroll 1
        for (int c = 0; c < 4; c++) {
            __half2 hb[16];
            const int cb = c * KC + gho;
#pragma unroll
            for (int u = 0; u < 16; u++) {
                int ci = cb + u * 2;
                float v0 = fmaf(r0v, __ldg(Wd1 + ci),
                           fmaf(r1v, __ldg(Wd1 + 256 + ci),
                           fmaf(r2v, __ldg(Wd1 + 512 + ci), __ldg(bd1 + ci))));
                float v1 = fmaf(r0v, __ldg(Wd1 + ci + 1),
                           fmaf(r1v, __ldg(Wd1 + 256 + ci + 1),
                           fmaf(r2v, __ldg(Wd1 + 512 + ci + 1), __ldg(bd1 + ci + 1))));
                hb[u] = __floats2half2_rn(fmaxf(v0, 0.f), fmaxf(v1, 0.f));
            }
            __half* dst = (__half*)(smraw + c * STG_B) + grow * SH + gho;
#pragma unroll
            for (int t = 0; t < 4; t++)
                *reinterpret_cast<uint4*>(dst + 8 * t) = *reinterpret_cast<uint4*>(&hb[4 * t]);
        }
    }

    float acc[4][4][4];
#pragma unroll
    for (int i = 0; i < 4; i++)
#pragma unroll
        for (int j = 0; j < 4; j++)
#pragma unroll
            for (int r = 0; r < 4; r++) acc[i][j][r] = 0.0f;

    const int rowbase = bm + wm * 64;

#pragma unroll 1
    for (int m = 0; m < 16; m++) {
        cp_wait<0>();
        __syncthreads();
        if (m < 15) issueB(m + 1);

        const uint32_t abase = sbase + (uint32_t)(m & 3) * STG_B + aoff;
        const uint32_t bbase = sbase + (uint32_t)(4 + (m & 1)) * STG_B + boff;

#pragma unroll
        for (int kk = 0; kk < 4; kk++) {
            uint32_t af[4][4], bf[4][2];
#pragma unroll
            for (int i = 0; i < 4; i++)
                LDSM_X4(af[i][0], af[i][1], af[i][2], af[i][3],
                        abase + i * (16 * SH * 2) + kk * 32);
#pragma unroll
            for (int jp = 0; jp < 2; jp++)
                LDSM_X4(bf[2*jp][0], bf[2*jp][1], bf[2*jp+1][0], bf[2*jp+1][1],
                        bbase + jp * (16 * SH * 2) + kk * 32);
#pragma unroll
            for (int i = 0; i < 4; i++)
#pragma unroll
                for (int j = 0; j < 4; j++)
                    mma_f16(acc[i][j], af[i], bf[j]);
        }

        if ((m & 3) == 3) {
            const int nt = m >> 2;
            const bool isPE = (nt < 2);
            const int colbase = nt * 128 + wn * 32 + tig * 2;
#pragma unroll
            for (int i = 0; i < 4; i++) {
                int r0 = rowbase + i * 16 + gid;
                int r1 = r0 + 8;
                int n = r0 >> 4;
                int j1 = 0, j2 = 0;
                if (!isPE) { j1 = smknn[r0 - bm]; j2 = smknn[r1 - bm]; }
#pragma unroll
                for (int j = 0; j < 4; j++) {
                    int col = colbase + j * 8;
                    if (isPE) {
                        float2 bb = *reinterpret_cast<const float2*>(bias + col);
                        *reinterpret_cast<__half2*>(pe_out + (size_t)r0 * DM + col) =
                            __floats2half2_rn(acc[i][j][0] + bb.x, acc[i][j][1] + bb.y);
                        *reinterpret_cast<__half2*>(pe_out + (size_t)r1 * DM + col) =
                            __floats2half2_rn(acc[i][j][2] + bb.x, acc[i][j][3] + bb.y);
                    } else {
                        int c2 = col - 256;
                        float2 ccv = *reinterpret_cast<const float2*>(cc + c2);
                        float2 qv  = *reinterpret_cast<const float2*>(qg + (size_t)n * DM + c2);
                        float2 k1  = __half22float2(*reinterpret_cast<const __half2*>(kg + (size_t)j1 * KVS + c2));
                        float2 k2  = __half22float2(*reinterpret_cast<const __half2*>(kg + (size_t)j2 * KVS + c2));
                        *reinterpret_cast<__half2*>(t2_out + (size_t)r0 * DM + c2) =
                            __floats2half2_rn(fmaxf(acc[i][j][0] + ccv.x + qv.x - k1.x, 0.f),
                                              fmaxf(acc[i][j][1] + ccv.y + qv.y - k1.y, 0.f));
                        *reinterpret_cast<__half2*>(t2_out + (size_t)r1 * DM + c2) =
                            __floats2half2_rn(fmaxf(acc[i][j][2] + ccv.x + qv.x - k2.x, 0.f),
                                              fmaxf(acc[i][j][3] + ccv.y + qv.y - k2.y, 0.f));
                    }
                }
            }
#pragma unroll
            for (int i = 0; i < 4; i++)
#pragma unroll
                for (int j = 0; j < 4; j++)
#pragma unroll
                    for (int r = 0; r < 4; r++) acc[i][j][r] = 0.0f;
        }
    }
}

// ---------------- host launch ----------------
template<int MODE, bool OUTH>
static void launch_h(int M, int N, int K,
                     const __half* A, const __half* WT,
                     const float* bias, const float* extra, void* Cout,
                     const __half* pe = nullptr, const __half* vf = nullptr,
                     __half* resh = nullptr, const int* knn = nullptr)
{
    cudaFuncSetAttribute(gemm_h<MODE, OUTH>,
                         cudaFuncAttributeMaxDynamicSharedMemorySize, GEMM_SMEM);
    gemm_h<MODE, OUTH><<<dim3(N / 128, M / 128), 256, GEMM_SMEM>>>(
        M, N, K, A, WT, bias, extra, Cout, pe, vf, resh, knn);
}

extern "C" void kernel_launch(void* const* d_in, const int* in_sizes, int n_in,
                              void* d_out, int out_size)
{
    const float* xyz1      = (const float*)d_in[0];
    const float* features1 = (const float*)d_in[1];
    const float* xyz2      = (const float*)d_in[2];
    const float* features2 = (const float*)d_in[3];
    const float* W_fc1     = (const float*)d_in[4];
    const float* b_fc1     = (const float*)d_in[5];
    const float* W_fc2     = (const float*)d_in[6];
    const float* b_fc2     = (const float*)d_in[7];
    const float* Wd1       = (const float*)d_in[8];
    const float* bd1       = (const float*)d_in[9];
    const float* Wd2       = (const float*)d_in[10];
    const float* bd2       = (const float*)d_in[11];
    const float* Wg1       = (const float*)d_in[12];
    const float* bg1       = (const float*)d_in[13];
    const float* Wg2       = (const float*)d_in[14];
    const float* bg2       = (const float*)d_in[15];
    const float* Wq        = (const float*)d_in[16];
    const float* Wk        = (const float*)d_in[17];
    const float* Wv        = (const float*)d_in[18];

    float* out_res  = (float*)d_out;
    float* out_attn = (float*)d_out + (size_t)BN * DP;

    int*    p_knn;  cudaGetSymbolAddress((void**)&p_knn,  g_knn);
    float4* p_sp4;  cudaGetSymbolAddress((void**)&p_sp4,  g_sp4);
    __half* p_f1h;  cudaGetSymbolAddress((void**)&p_f1h,  g_f1h);
    __half* p_f2h;  cudaGetSymbolAddress((void**)&p_f2h,  g_f2h);
    __half* p_x1h;  cudaGetSymbolAddress((void**)&p_x1h,  g_x1h);
    __half* p_x2h;  cudaGetSymbolAddress((void**)&p_x2h,  g_x2h);
    float*  p_qg;   cudaGetSymbolAddress((void**)&p_qg,   g_qg);
    __half* p_kgvf; cudaGetSymbolAddress((void**)&p_kgvf, g_kgvfh);
    __half* p_resh; cudaGetSymbolAddress((void**)&p_resh, g_resh);
    __half* p_t2h;  cudaGetSymbolAddress((void**)&p_t2h,  g_t2h);
    __half* p_peh;  cudaGetSymbolAddress((void**)&p_peh,  g_peh);
    __half* w_fc1;  cudaGetSymbolAddress((void**)&w_fc1,  g_wfc1h);
    __half* w_fc2;  cudaGetSymbolAddress((void**)&w_fc2,  g_wfc2h);
    __half* w_dual; cudaGetSymbolAddress((void**)&w_dual, g_wdualh);
    __half* w_g2;   cudaGetSymbolAddress((void**)&w_g2,   g_wg2h);
    __half* w_qg;   cudaGetSymbolAddress((void**)&w_qg,   g_wqgh);
    __half* w_kv;   cudaGetSymbolAddress((void**)&w_kv,   g_wkvh);
    float*  p_cc;   cudaGetSymbolAddress((void**)&p_cc,   g_cc);

    cudaFuncSetAttribute(gen_dual_kernel,
                         cudaFuncAttributeMaxDynamicSharedMemorySize, GEN_SMEM);

    static cudaStream_t sB = nullptr;
    static cudaEvent_t evF = nullptr, evJ = nullptr;
    if (sB == nullptr) {
        cudaStreamCreateWithFlags(&sB, cudaStreamNonBlocking);
        cudaEventCreateWithFlags(&evF, cudaEventDisableTiming);
        cudaEventCreateWithFlags(&evJ, cudaEventDisableTiming);
    }

    dim3 tb(32, 8);

    // ---- fork: stream B runs the KNN branch ----
    cudaEventRecord(evF, 0);
    cudaStreamWaitEvent(sB, evF, 0);
    prep_pts<<<BN / 256, 256, 0, sB>>>(xyz2, p_sp4);
    knn_kernel<<<BN / 8, 256, 0, sB>>>(xyz1, p_sp4, p_knn);
    cudaEventRecord(evJ, sB);

    // ---- stream 0: tensor-bound prep + projection chain ----
    transpose_kernel<<<dim3(DM/32, DP/32), tb>>>(W_fc1, w_fc1, DP, DM);
    f2h_kernel<<<(BN * DP) / 1024, 256>>>(features1, p_f1h);
    f2h_kernel<<<(BN * DP) / 1024, 256>>>(features2, p_f2h);
    transpose_kernel<<<dim3(DM/32, DM/32), tb>>>(Wd2,  w_dual, DM, DM);
    transpose_kernel<<<dim3(DM/32, DM/32), tb>>>(Wg2,  w_g2, DM, DM);
    transpose_kernel<<<dim3(DM/32, DM/32), tb>>>(Wv,   w_kv + DM * DM, DM, DM);
    transpose_kernel<<<dim3(DP/32, DM/32), tb>>>(W_fc2, w_fc2, DM, DP);
    combine_kernel<<<DM, DM>>>(Wq,  Wg1, w_qg);
    combine_kernel<<<DM, DM>>>(Wk,  Wg1, w_kv);
    combine_kernel<<<DM, DM>>>(Wd2, Wg1, w_dual + DM * DM);
    cc_kernel<<<1, DM>>>(bd2, Wg1, bg1, p_cc);

    launch_h<0, true >(BN, DM, DP, p_f1h, w_fc1, b_fc1, nullptr, p_x1h);
    launch_h<0, true >(BN, DM, DP, p_f2h, w_fc1, b_fc1, nullptr, p_x2h);
    launch_h<0, false>(BN, DM, DM, p_x1h, w_qg, nullptr, nullptr, p_qg);
    launch_h<0, true >(BN, KVS, DM, p_x2h, w_kv, nullptr, nullptr, p_kgvf);

    // ---- join: gen_dual needs knn + qg + kgvf ----
    cudaStreamWaitEvent(0, evJ, 0);

    gen_dual_kernel<<<BNK / 128, 256, GEN_SMEM>>>(
        w_dual, xyz1, xyz2, Wd1, bd1, bd2, p_peh, p_t2h, p_cc, p_qg, p_kgvf, p_knn);

    launch_h<2, false>(BNK, DM, DM, p_t2h, w_g2, bg2, nullptr, out_attn,
                       p_peh, p_kgvf + 256, p_resh, p_knn);

    launch_h<0, false>(BN, DP, DM, p_resh, w_fc2, b_fc2, features1, out_res);
}